// round 1
// baseline (speedup 1.0000x reference)
#include <cuda_runtime.h>

// ---------------------------------------------------------------------------
// AnchorRefine: Faster R-CNN RPN anchor-target assignment.
//   N=32 images, A=36864 anchors, M=32 gt boxes, TOTAL=256 kept, MAX_FG=128.
// Outputs (assumed concatenated into one f32 buffer, 49152 elements):
//   [0,8192)      idx        (int -> float)
//   [8192,16384)  fg_mask    (bool -> float)
//   [16384,49152) target_coeff [N,256,4]
// ---------------------------------------------------------------------------

#define AN     36864
#define NI     32
#define MG     32
#define TOTAL_K 256
#define MAXFG  128
#define POS_T  0.7f
#define NEG_T  0.3f
#define IMGSZ  1024.0f
#define NBUCK  4096
#define CAPL   2048
#define SLICES 16

// ----- device scratch (static; no allocations allowed) ---------------------
__device__ float          g_amax [NI * AN];
__device__ unsigned char  g_gtid [NI * AN];
__device__ signed char    g_label[NI * AN];
__device__ unsigned       g_pgm  [NI * MG];            // ordered-encoded per-gt max
__device__ unsigned       g_hist [NI * 2 * NBUCK];     // [n][class][bucket], class 0=bg,1=fg
__device__ unsigned       g_cnt  [NI * 2];             // [n][class]
__device__ unsigned long long g_cut[NI * 2];           // [n][class] key cutoffs

// ----- helpers -------------------------------------------------------------
__device__ __forceinline__ unsigned encf(float f) {
    unsigned b = __float_as_uint(f);
    return (b & 0x80000000u) ? ~b : (b | 0x80000000u);
}
__device__ __forceinline__ float decf(unsigned u) {
    unsigned b = (u & 0x80000000u) ? (u ^ 0x80000000u) : ~u;
    return __uint_as_float(b);
}
__device__ __forceinline__ int bucketf(float r) {
    int b = (int)(r * 4096.0f);
    return b < 0 ? 0 : (b > 4095 ? 4095 : b);
}
// key reproducing rank_desc with stable tie-break (r desc, idx asc). r >= 0.
__device__ __forceinline__ unsigned long long keyf(float r, int a) {
    return (((unsigned long long)__float_as_uint(r)) << 32)
         | (unsigned)(0xFFFFFFFFu - (unsigned)a);
}

// bbox_transform, exact op order of the reference, no FMA contraction.
__device__ __forceinline__ void predbox(float4 an, float4 d, float* b, float* areaA, bool* valid) {
    float w  = __fadd_rn(__fsub_rn(an.z, an.x), 1.0f);
    float h  = __fadd_rn(__fsub_rn(an.w, an.y), 1.0f);
    float cx = __fadd_rn(an.x, __fmul_rn(0.5f, w));
    float cy = __fadd_rn(an.y, __fmul_rn(0.5f, h));
    float pcx = __fadd_rn(__fmul_rn(d.x, w), cx);
    float pcy = __fadd_rn(__fmul_rn(d.y, h), cy);
    float pw  = __fmul_rn(expf(d.z), w);
    float ph  = __fmul_rn(expf(d.w), h);
    b[0] = __fsub_rn(pcx, __fmul_rn(0.5f, pw));
    b[1] = __fsub_rn(pcy, __fmul_rn(0.5f, ph));
    b[2] = __fadd_rn(pcx, __fmul_rn(0.5f, pw));
    b[3] = __fadd_rn(pcy, __fmul_rn(0.5f, ph));
    *areaA = __fmul_rn(__fadd_rn(__fsub_rn(b[2], b[0]), 1.0f),
                       __fadd_rn(__fsub_rn(b[3], b[1]), 1.0f));
    *valid = (b[0] >= 0.0f) && (b[1] >= 0.0f) && (b[2] < IMGSZ) && (b[3] < IMGSZ);
}

__device__ __forceinline__ float iouf(const float* b, float areaA, float4 g, float ag) {
    float iw = fmaxf(__fadd_rn(__fsub_rn(fminf(b[2], g.z), fmaxf(b[0], g.x)), 1.0f), 0.0f);
    float ih = fmaxf(__fadd_rn(__fsub_rn(fminf(b[3], g.w), fmaxf(b[1], g.y)), 1.0f), 0.0f);
    float inter = __fmul_rn(iw, ih);
    return __fdiv_rn(inter, __fsub_rn(__fadd_rn(areaA, ag), inter));
}

// ----- K0: init scratch ----------------------------------------------------
__global__ void k_init() {
    int i = blockIdx.x * blockDim.x + threadIdx.x;
    if (i < NI * MG)        g_pgm[i] = 0x407FFFFFu;   // encf(-1.0f)
    if (i < NI * 2)         g_cnt[i] = 0u;
    if (i < NI * 2 * NBUCK) g_hist[i] = 0u;
}

// ----- K1: pred boxes, IoU, anchor_max/argmax, per-gt max, provisional label
__global__ void __launch_bounds__(256) k_pass1(const float* __restrict__ anchors,
                                               const float* __restrict__ gtb,
                                               const float* __restrict__ deltas) {
    int n = blockIdx.y;
    int tid = threadIdx.x;
    __shared__ float4 sg[MG];
    __shared__ float  sga[MG];
    if (tid < MG) {
        float4 g = ((const float4*)gtb)[n * MG + tid];
        sg[tid] = g;
        sga[tid] = __fmul_rn(__fadd_rn(__fsub_rn(g.z, g.x), 1.0f),
                             __fadd_rn(__fsub_rn(g.w, g.y), 1.0f));
    }
    __syncthreads();

    float lmax[MG];
#pragma unroll
    for (int m = 0; m < MG; m++) lmax[m] = -1.0f;

    const int per = AN / SLICES;
    const int a0 = blockIdx.x * per;
    for (int a = a0 + tid; a < a0 + per; a += blockDim.x) {
        float4 an = ((const float4*)anchors)[a];
        float4 d  = ((const float4*)deltas)[n * AN + a];
        float b[4], areaA; bool valid;
        predbox(an, d, b, &areaA, &valid);

        float amax = -1.0f; int gid = 0;
        if (valid) {
            amax = -2.0f;
#pragma unroll
            for (int m = 0; m < MG; m++) {
                float ov = iouf(b, areaA, sg[m], sga[m]);
                if (ov > lmax[m]) lmax[m] = ov;
                if (ov > amax) { amax = ov; gid = m; }  // strict > == first argmax
            }
        }
        g_amax[n * AN + a] = amax;
        g_gtid[n * AN + a] = (unsigned char)gid;
        signed char lab = (amax >= POS_T) ? 1 : ((amax >= 0.0f && amax < NEG_T) ? 0 : -1);
        g_label[n * AN + a] = lab;
    }

    // reduce per-gt maxima: warp shuffle then global atomicMax on ordered bits
#pragma unroll
    for (int m = 0; m < MG; m++) {
        float v = lmax[m];
        for (int off = 16; off; off >>= 1)
            v = fmaxf(v, __shfl_xor_sync(0xFFFFFFFFu, v, off));
        if ((tid & 31) == 0) atomicMax(&g_pgm[n * MG + m], encf(v));
    }
}

// ----- K2: a_box upgrade (pruned) + class histograms ------------------------
__global__ void __launch_bounds__(256) k_pass2(const float* __restrict__ anchors,
                                               const float* __restrict__ gtb,
                                               const float* __restrict__ deltas,
                                               const float* __restrict__ rs) {
    int n = blockIdx.y;
    int tid = threadIdx.x;
    __shared__ float4 sg[MG];
    __shared__ float  sga[MG];
    __shared__ float  spgm[MG];
    __shared__ float  sminp;
    if (tid < MG) {
        float4 g = ((const float4*)gtb)[n * MG + tid];
        sg[tid] = g;
        sga[tid] = __fmul_rn(__fadd_rn(__fsub_rn(g.z, g.x), 1.0f),
                             __fadd_rn(__fsub_rn(g.w, g.y), 1.0f));
        spgm[tid] = decf(g_pgm[n * MG + tid]);
    }
    __syncthreads();
    if (tid == 0) {
        float mn = spgm[0];
        for (int m = 1; m < MG; m++) mn = fminf(mn, spgm[m]);
        sminp = mn;
    }
    __syncthreads();

    const int per = AN / SLICES;
    const int a0 = blockIdx.x * per;
    for (int a = a0 + tid; a < a0 + per; a += blockDim.x) {
        signed char lab = g_label[n * AN + a];
        float amax = g_amax[n * AN + a];
        // a_box possible only if valid (amax>=0) and amax >= min per-gt max
        if (lab != 1 && amax >= 0.0f && amax >= sminp) {
            float4 an = ((const float4*)anchors)[a];
            float4 d  = ((const float4*)deltas)[n * AN + a];
            float b[4], areaA; bool valid;
            predbox(an, d, b, &areaA, &valid);
            bool abox = false;
#pragma unroll
            for (int m = 0; m < MG; m++) {
                float ov = iouf(b, areaA, sg[m], sga[m]);  // bitwise == pass-1 value
                abox |= (ov == spgm[m]);
            }
            if (abox) { lab = 1; g_label[n * AN + a] = 1; }
        }
        if (lab >= 0) {
            float r = rs[n * AN + a];
            atomicAdd(&g_hist[(n * 2 + lab) * NBUCK + bucketf(r)], 1u);
            atomicAdd(&g_cnt[n * 2 + lab], 1u);
        }
    }
}

// ----- K3: per-image top-k cutoff keys (radix-select on r buckets) ----------
__global__ void __launch_bounds__(256) k_select(const float* __restrict__ rs) {
    int n = blockIdx.x;
    int tid = threadIdx.x;
    __shared__ unsigned seg[256];
    __shared__ int sbF, sbB;
    __shared__ unsigned sneedF, sneedB;
    __shared__ unsigned long long listF[CAPL];
    __shared__ unsigned long long listB[CAPL];
    __shared__ unsigned cntF, cntB;
    __shared__ unsigned long long scutF, scutB;

    unsigned nfg = g_cnt[n * 2 + 1];
    unsigned nbg = g_cnt[n * 2 + 0];
    unsigned keptfg = nfg < MAXFG ? nfg : MAXFG;
    unsigned quota = TOTAL_K - keptfg;
    if (tid == 0) { sbF = -1; sbB = -1; cntF = 0; cntB = 0; scutF = 0ull; scutB = 0ull; }
    __syncthreads();

    // fg boundary bucket
    if (nfg > MAXFG) {
        const unsigned* h = &g_hist[(n * 2 + 1) * NBUCK];
        unsigned p = 0;
        for (int j = 0; j < 16; j++) p += h[4095 - (tid * 16 + j)];
        seg[tid] = p;
        __syncthreads();
        if (tid == 0) {
            unsigned cum = 0; int t = 0;
            while (cum + seg[t] < MAXFG) { cum += seg[t]; t++; }
            for (int j = 0; j < 16; j++) {
                int bb = 4095 - (t * 16 + j);
                unsigned c = h[bb];
                if (cum + c >= MAXFG) { sbF = bb; sneedF = MAXFG - cum; break; }
                cum += c;
            }
        }
        __syncthreads();
    }
    // bg boundary bucket
    if (nbg > quota) {
        const unsigned* h = &g_hist[(n * 2 + 0) * NBUCK];
        unsigned p = 0;
        for (int j = 0; j < 16; j++) p += h[4095 - (tid * 16 + j)];
        seg[tid] = p;
        __syncthreads();
        if (tid == 0) {
            unsigned cum = 0; int t = 0;
            while (cum + seg[t] < quota) { cum += seg[t]; t++; }
            for (int j = 0; j < 16; j++) {
                int bb = 4095 - (t * 16 + j);
                unsigned c = h[bb];
                if (cum + c >= quota) { sbB = bb; sneedB = quota - cum; break; }
                cum += c;
            }
        }
        __syncthreads();
    }

    // collect boundary-bucket keys
    if (sbF >= 0 || sbB >= 0) {
        for (int a = tid; a < AN; a += blockDim.x) {
            signed char lab = g_label[n * AN + a];
            if (lab < 0) continue;
            float r = rs[n * AN + a];
            int b = bucketf(r);
            if (lab == 1 && b == sbF) {
                unsigned p = atomicAdd(&cntF, 1u);
                if (p < CAPL) listF[p] = keyf(r, a);
            } else if (lab == 0 && b == sbB) {
                unsigned p = atomicAdd(&cntB, 1u);
                if (p < CAPL) listB[p] = keyf(r, a);
            }
        }
    }
    __syncthreads();

    // exact need-th largest key inside the boundary bucket (keys are distinct)
    if (sbF >= 0) {
        unsigned L = cntF < CAPL ? cntF : CAPL;
        for (unsigned i = tid; i < L; i += blockDim.x) {
            unsigned long long k = listF[i];
            unsigned c = 0;
            for (unsigned j = 0; j < L; j++) c += (listF[j] > k);
            if (c == sneedF - 1) scutF = k;
        }
    }
    if (sbB >= 0) {
        unsigned L = cntB < CAPL ? cntB : CAPL;
        for (unsigned i = tid; i < L; i += blockDim.x) {
            unsigned long long k = listB[i];
            unsigned c = 0;
            for (unsigned j = 0; j < L; j++) c += (listB[j] > k);
            if (c == sneedB - 1) scutB = k;
        }
    }
    __syncthreads();
    if (tid == 0) {
        g_cut[n * 2 + 1] = (nfg > MAXFG) ? scutF : 0ull;
        g_cut[n * 2 + 0] = (nbg > quota) ? scutB : 0ull;
    }
}

// ----- K4: ordered compaction + outputs -------------------------------------
__device__ __forceinline__ void write_out(float* out, int n, unsigned p, int a,
                                          bool fg, const float4* sg,
                                          const float* anchors) {
    int gi = g_gtid[n * AN + a];
    float4 A4 = ((const float4*)anchors)[a];
    float4 G = sg[gi];
    float aw = A4.z - A4.x + 1.0f, ah = A4.w - A4.y + 1.0f;
    float acx = A4.x + 0.5f * aw, acy = A4.y + 0.5f * ah;
    float gw = G.z - G.x + 1.0f, gh = G.w - G.y + 1.0f;
    float gcx = G.x + 0.5f * gw, gcy = G.y + 0.5f * gh;
    out[n * TOTAL_K + p] = (float)a;
    out[NI * TOTAL_K + n * TOTAL_K + p] = fg ? 1.0f : 0.0f;
    float* c = &out[2 * NI * TOTAL_K + (unsigned)(n * TOTAL_K + p) * 4u];
    c[0] = (gcx - acx) / aw;
    c[1] = (gcy - acy) / ah;
    c[2] = logf(gw / aw);
    c[3] = logf(gh / ah);
}

__global__ void __launch_bounds__(512) k_out(const float* __restrict__ anchors,
                                             const float* __restrict__ gtb,
                                             const float* __restrict__ rs,
                                             float* __restrict__ out) {
    int n = blockIdx.x;
    int tid = threadIdx.x;
    int wid = tid >> 5, lane = tid & 31;
    __shared__ float4 sg[MG];
    __shared__ unsigned swoff[16];
    __shared__ unsigned sbase;
    if (tid < MG) sg[tid] = ((const float4*)gtb)[n * MG + tid];
    if (tid == 0) sbase = 0;
    unsigned long long cutF = g_cut[n * 2 + 1];
    unsigned long long cutB = g_cut[n * 2 + 0];
    __syncthreads();

    for (int start = 0; start < AN; start += 512) {
        int a = start + tid;
        signed char lab = g_label[n * AN + a];
        bool kept = false, isfg = false;
        if (lab >= 0) {
            unsigned long long k = keyf(rs[n * AN + a], a);
            if (lab == 1) { kept = (k >= cutF); isfg = kept; }
            else          { kept = (k >= cutB); }
        }
        unsigned bal = __ballot_sync(0xFFFFFFFFu, kept);
        unsigned pre = __popc(bal & ((1u << lane) - 1u));
        if (lane == 0) swoff[wid] = __popc(bal);
        __syncthreads();
        if (tid == 0) {
            unsigned run = sbase;
            for (int w = 0; w < 16; w++) { unsigned t = swoff[w]; swoff[w] = run; run += t; }
            sbase = run;
        }
        __syncthreads();
        if (kept) {
            unsigned p = swoff[wid] + pre;
            if (p < TOTAL_K) write_out(out, n, p, a, isfg, sg, anchors);
        }
        __syncthreads();
    }

    if (tid == 0) {
        unsigned tot = sbase;
        if (tot < TOTAL_K) {
            signed char lab0 = g_label[n * AN + 0];
            bool fg0 = false;
            if (lab0 == 1) fg0 = (keyf(rs[n * AN], 0) >= cutF);
            for (unsigned p = tot; p < TOTAL_K; p++)
                write_out(out, n, p, 0, fg0, sg, anchors);
        }
    }
}

// ----- launch ----------------------------------------------------------------
extern "C" void kernel_launch(void* const* d_in, const int* in_sizes, int n_in,
                              void* d_out, int out_size) {
    // match inputs by element count (robust to metadata ordering)
    const float *anchors = nullptr, *gtb = nullptr, *deltas = nullptr, *rsc = nullptr;
    for (int i = 0; i < n_in; i++) {
        int s = in_sizes[i];
        if (s == AN * 4)           anchors = (const float*)d_in[i];
        else if (s == NI * MG * 4) gtb     = (const float*)d_in[i];
        else if (s == NI * AN * 4) deltas  = (const float*)d_in[i];
        else if (s == NI * AN)     rsc     = (const float*)d_in[i];
    }
    float* out = (float*)d_out;

    k_init<<<(NI * 2 * NBUCK + 255) / 256, 256>>>();
    dim3 g1(SLICES, NI);
    k_pass1<<<g1, 256>>>(anchors, gtb, deltas);
    k_pass2<<<g1, 256>>>(anchors, gtb, deltas, rsc);
    k_select<<<NI, 256>>>(rsc);
    k_out<<<NI, 512>>>(anchors, gtb, rsc, out);
}

// round 2
// speedup vs baseline: 4.4898x; 4.4898x over previous
#include <cuda_runtime.h>

// ---------------------------------------------------------------------------
// AnchorRefine R2: type-major warp-coherent IoU passes, zero-inter early-out,
// histogram-derived counts, vectorized select, collect+sort compaction.
//   N=32 images, A=36864 anchors (4096 positions x 9 types), M=32 gt,
//   TOTAL=256 kept, MAX_FG=128.
// Output f32 buffer 49152: [0,8192) idx, [8192,16384) fg, [16384,49152) coeff.
// Scratch layout uses a' = type*4096 + pos (coalesced); real a = pos*9 + type.
// ---------------------------------------------------------------------------

#define AN      36864
#define NPOS    4096
#define NTYPE   9
#define NI      32
#define MG      32
#define TOTAL_K 256
#define MAXFG   128
#define POS_T   0.7f
#define NEG_T   0.3f
#define IMGSZ   1024.0f
#define NBUCK   4096
#define CAPL    512
#define PCHUNK  256          // positions per CTA in pass kernels

// ----- device scratch ------------------------------------------------------
__device__ __align__(16) float         g_amax [NI * AN];   // [n][a']
__device__ __align__(16) signed char   g_label[NI * AN];   // [n][a']
__device__ unsigned                    g_pgm  [NI * MG];   // ordered-encoded per-gt max
__device__ unsigned                    g_hist [NI * 2 * NBUCK];
__device__ unsigned long long          g_cut  [NI * 2];

// ----- helpers -------------------------------------------------------------
__device__ __forceinline__ unsigned encf(float f) {
    unsigned b = __float_as_uint(f);
    return (b & 0x80000000u) ? ~b : (b | 0x80000000u);
}
__device__ __forceinline__ float decf(unsigned u) {
    unsigned b = (u & 0x80000000u) ? (u ^ 0x80000000u) : ~u;
    return __uint_as_float(b);
}
__device__ __forceinline__ int bucketf(float r) {
    int b = (int)(r * 4096.0f);
    return b < 0 ? 0 : (b > 4095 ? 4095 : b);
}
__device__ __forceinline__ unsigned long long keyf(float r, int a) {
    return (((unsigned long long)__float_as_uint(r)) << 32)
         | (unsigned)(0xFFFFFFFFu - (unsigned)a);
}

// bbox_transform, exact reference op order, no FMA contraction.
__device__ __forceinline__ void predbox(float4 an, float4 d, float* b,
                                        float* areaA, bool* valid) {
    float w  = __fadd_rn(__fsub_rn(an.z, an.x), 1.0f);
    float h  = __fadd_rn(__fsub_rn(an.w, an.y), 1.0f);
    float cx = __fadd_rn(an.x, __fmul_rn(0.5f, w));
    float cy = __fadd_rn(an.y, __fmul_rn(0.5f, h));
    float pcx = __fadd_rn(__fmul_rn(d.x, w), cx);
    float pcy = __fadd_rn(__fmul_rn(d.y, h), cy);
    float pw  = __fmul_rn(expf(d.z), w);
    float ph  = __fmul_rn(expf(d.w), h);
    b[0] = __fsub_rn(pcx, __fmul_rn(0.5f, pw));
    b[1] = __fsub_rn(pcy, __fmul_rn(0.5f, ph));
    b[2] = __fadd_rn(pcx, __fmul_rn(0.5f, pw));
    b[3] = __fadd_rn(pcy, __fmul_rn(0.5f, ph));
    *areaA = __fmul_rn(__fadd_rn(__fsub_rn(b[2], b[0]), 1.0f),
                       __fadd_rn(__fsub_rn(b[3], b[1]), 1.0f));
    *valid = (b[0] >= 0.0f) && (b[1] >= 0.0f) && (b[2] < IMGSZ) && (b[3] < IMGSZ);
}

// exact IoU (bitwise identical across all kernels)
__device__ __forceinline__ float iou_div(float inter, float areaA, float ag) {
    return __fdiv_rn(inter, __fsub_rn(__fadd_rn(areaA, ag), inter));
}

// ----- K0: init ------------------------------------------------------------
__global__ void k_init() {
    int i = blockIdx.x * blockDim.x + threadIdx.x;
    if (i < NI * MG)        g_pgm[i] = 0x407FFFFFu;   // encf(-1.0f)
    if (i < NI * 2 * NBUCK) g_hist[i] = 0u;
}

// ----- K1: pred boxes, anchor_max, per-gt max, provisional label -----------
__global__ void __launch_bounds__(256) k_pass1(const float* __restrict__ anchors,
                                               const float* __restrict__ gtb,
                                               const float* __restrict__ deltas) {
    const int n = blockIdx.y;
    const int tid = threadIdx.x;
    const int p = blockIdx.x * PCHUNK + tid;          // position, warp-coherent
    __shared__ float4 sg[MG];
    __shared__ float  sga[MG];
    __shared__ float  sred[8][MG];
    if (tid < MG) {
        float4 g = ((const float4*)gtb)[n * MG + tid];
        sg[tid] = g;
        sga[tid] = __fmul_rn(__fadd_rn(__fsub_rn(g.z, g.x), 1.0f),
                             __fadd_rn(__fsub_rn(g.w, g.y), 1.0f));
    }
    __syncthreads();

    float lmax[MG];
#pragma unroll
    for (int m = 0; m < MG; m++) lmax[m] = -1.0f;
    bool anyv = false;

    for (int type = 0; type < NTYPE; type++) {
        const int a  = p * NTYPE + type;              // original index
        const int ap = type * NPOS + p;               // coalesced scratch index
        float4 an = ((const float4*)anchors)[a];
        float4 d  = ((const float4*)deltas)[n * AN + a];
        float b[4], areaA; bool valid;
        predbox(an, d, b, &areaA, &valid);

        float amax = -1.0f;
        if (valid) {
            anyv = true;
            amax = 0.0f;
#pragma unroll 4
            for (int m = 0; m < MG; m++) {
                float4 g = sg[m];
                float iw = __fadd_rn(__fsub_rn(fminf(b[2], g.z), fmaxf(b[0], g.x)), 1.0f);
                float ih = __fadd_rn(__fsub_rn(fminf(b[3], g.w), fmaxf(b[1], g.y)), 1.0f);
                if (iw > 0.0f && ih > 0.0f) {
                    float inter = __fmul_rn(iw, ih);
                    float ov = iou_div(inter, areaA, sga[m]);
                    amax = fmaxf(amax, ov);
                    lmax[m] = fmaxf(lmax[m], ov);
                }
            }
        }
        g_amax[n * AN + ap] = amax;
        signed char lab = (amax >= POS_T) ? 1 : ((amax >= 0.0f && amax < NEG_T) ? 0 : -1);
        g_label[n * AN + ap] = lab;
    }

    // per-gt max reduction: warp shuffle -> shared -> 32 atomics per CTA
    const int wid = tid >> 5, lane = tid & 31;
#pragma unroll
    for (int m = 0; m < MG; m++) {
        float v = lmax[m];
        for (int off = 16; off; off >>= 1)
            v = fmaxf(v, __shfl_xor_sync(0xFFFFFFFFu, v, off));
        if (lane == 0) sred[wid][m] = v;
    }
    int anyv_all = __syncthreads_or(anyv ? 1 : 0);
    if (tid < MG) {
        float v = sred[0][tid];
#pragma unroll
        for (int w = 1; w < 8; w++) v = fmaxf(v, sred[w][tid]);
        if (anyv_all) v = fmaxf(v, 0.0f);   // valid anchors give ov >= 0 baseline
        atomicMax(&g_pgm[n * MG + tid], encf(v));
    }
}

// ----- K2: a_box upgrade (gated) + class histograms ------------------------
__global__ void __launch_bounds__(256) k_pass2(const float* __restrict__ anchors,
                                               const float* __restrict__ gtb,
                                               const float* __restrict__ deltas,
                                               const float* __restrict__ rs) {
    const int n = blockIdx.y;
    const int tid = threadIdx.x;
    const int p = blockIdx.x * PCHUNK + tid;
    __shared__ float4 sg[MG];
    __shared__ float  sga[MG];
    __shared__ float  spgm[MG];
    __shared__ float  sminp;
    if (tid < MG) {
        float4 g = ((const float4*)gtb)[n * MG + tid];
        sg[tid] = g;
        sga[tid] = __fmul_rn(__fadd_rn(__fsub_rn(g.z, g.x), 1.0f),
                             __fadd_rn(__fsub_rn(g.w, g.y), 1.0f));
        spgm[tid] = decf(g_pgm[n * MG + tid]);
    }
    __syncthreads();
    if (tid == 0) {
        float mn = spgm[0];
        for (int m = 1; m < MG; m++) mn = fminf(mn, spgm[m]);
        sminp = mn;
    }
    __syncthreads();

    for (int type = 0; type < NTYPE; type++) {
        const int a  = p * NTYPE + type;
        const int ap = type * NPOS + p;
        signed char lab = g_label[n * AN + ap];
        if (lab != 1) {
            float amax = g_amax[n * AN + ap];
            if (amax >= 0.0f && amax >= sminp) {     // necessary for a_box
                float4 an = ((const float4*)anchors)[a];
                float4 d  = ((const float4*)deltas)[n * AN + a];
                float b[4], areaA; bool valid;
                predbox(an, d, b, &areaA, &valid);
                bool abox = false;
#pragma unroll 4
                for (int m = 0; m < MG; m++) {
                    float pm = spgm[m];
                    if (pm <= amax) {                // ov <= amax, need ov == pm
                        float4 g = sg[m];
                        float iw = __fadd_rn(__fsub_rn(fminf(b[2], g.z), fmaxf(b[0], g.x)), 1.0f);
                        float ih = __fadd_rn(__fsub_rn(fminf(b[3], g.w), fmaxf(b[1], g.y)), 1.0f);
                        if (iw > 0.0f && ih > 0.0f) {
                            float inter = __fmul_rn(iw, ih);
                            float ov = iou_div(inter, areaA, sga[m]);
                            abox |= (ov == pm);
                        } else {
                            abox |= (pm == 0.0f);    // ov == 0 case
                        }
                    }
                }
                if (abox) { lab = 1; g_label[n * AN + ap] = 1; }
            }
        }
        if (lab >= 0) {
            float r = rs[n * AN + a];
            atomicAdd(&g_hist[(n * 2 + lab) * NBUCK + bucketf(r)], 1u);
        }
    }
}

// ----- K3: per-image top-k cutoff keys -------------------------------------
__global__ void __launch_bounds__(256) k_select(const float* __restrict__ rs) {
    const int n = blockIdx.x;
    const int tid = threadIdx.x;
    __shared__ unsigned segF[256], segB[256];
    __shared__ int sbF, sbB, hasF, hasB;
    __shared__ unsigned sneedF, sneedB;
    __shared__ unsigned long long listF[CAPL], listB[CAPL];
    __shared__ unsigned cntF, cntB;
    __shared__ unsigned long long scutF, scutB;

    const unsigned* hF = &g_hist[(n * 2 + 1) * NBUCK];
    const unsigned* hB = &g_hist[(n * 2 + 0) * NBUCK];
    unsigned pF = 0, pB = 0;
#pragma unroll
    for (int j = 0; j < 16; j++) {
        int b = 4095 - (tid * 16 + j);
        pF += hF[b];
        pB += hB[b];
    }
    segF[tid] = pF; segB[tid] = pB;
    if (tid == 0) { sbF = -1; sbB = -1; cntF = 0; cntB = 0;
                    scutF = 0ull; scutB = 0ull; hasF = 0; hasB = 0; }
    __syncthreads();

    if (tid == 0) {
        unsigned totF = 0, totB = 0;
        for (int t = 0; t < 256; t++) { totF += segF[t]; totB += segB[t]; }
        unsigned keptfg = totF < MAXFG ? totF : MAXFG;
        unsigned quota = TOTAL_K - keptfg;
        if (totF > MAXFG) {
            hasF = 1;
            unsigned cum = 0; int t = 0;
            while (t < 255 && cum + segF[t] < MAXFG) { cum += segF[t]; t++; }
            for (int j = 0; j < 16; j++) {
                int bb = 4095 - (t * 16 + j);
                unsigned c = hF[bb];
                if (cum + c >= MAXFG) { sbF = bb; sneedF = MAXFG - cum; break; }
                cum += c;
            }
        }
        if (totB > quota) {
            hasB = 1;
            unsigned cum = 0; int t = 0;
            while (t < 255 && cum + segB[t] < quota) { cum += segB[t]; t++; }
            for (int j = 0; j < 16; j++) {
                int bb = 4095 - (t * 16 + j);
                unsigned c = hB[bb];
                if (cum + c >= quota) { sbB = bb; sneedB = quota - cum; break; }
                cum += c;
            }
        }
    }
    __syncthreads();

    if (sbF >= 0 || sbB >= 0) {
        const unsigned long long* lp =
            (const unsigned long long*)(g_label + (size_t)n * AN);
#pragma unroll
        for (int i = 0; i < 18; i++) {
            unsigned long long v = lp[tid * 18 + i];
#pragma unroll
            for (int j = 0; j < 8; j++) {
                signed char lab = (signed char)((v >> (j * 8)) & 0xFF);
                if (lab < 0) continue;
                int ap = (tid * 18 + i) * 8 + j;
                int a = (ap & (NPOS - 1)) * NTYPE + (ap >> 12);
                float r = rs[n * AN + a];
                int b = bucketf(r);
                if (lab == 1 && b == sbF) {
                    unsigned q = atomicAdd(&cntF, 1u);
                    if (q < CAPL) listF[q] = keyf(r, a);
                } else if (lab == 0 && b == sbB) {
                    unsigned q = atomicAdd(&cntB, 1u);
                    if (q < CAPL) listB[q] = keyf(r, a);
                }
            }
        }
    }
    __syncthreads();

    if (sbF >= 0) {
        unsigned L = cntF < CAPL ? cntF : CAPL;
        for (unsigned i = tid; i < L; i += 256) {
            unsigned long long k = listF[i];
            unsigned c = 0;
            for (unsigned j = 0; j < L; j++) c += (listF[j] > k);
            if (c == sneedF - 1) scutF = k;
        }
    }
    if (sbB >= 0) {
        unsigned L = cntB < CAPL ? cntB : CAPL;
        for (unsigned i = tid; i < L; i += 256) {
            unsigned long long k = listB[i];
            unsigned c = 0;
            for (unsigned j = 0; j < L; j++) c += (listB[j] > k);
            if (c == sneedB - 1) scutB = k;
        }
    }
    __syncthreads();
    if (tid == 0) {
        g_cut[n * 2 + 1] = hasF ? scutF : 0ull;
        g_cut[n * 2 + 0] = hasB ? scutB : 0ull;
    }
}

// ----- K4: collect kept, sort by anchor index, write outputs ----------------
__device__ __forceinline__ void write_out(float* out, int n, unsigned p, int a,
                                          bool fg, const float4* sg,
                                          const float* anchors,
                                          const float* deltasImg) {
    // gt_id = first argmax over m of masked IoU row (recomputed exactly)
    float4 A4 = ((const float4*)anchors)[a];
    float4 d  = ((const float4*)deltasImg)[0];  // placeholder, overwritten below
    d = ((const float4*)deltasImg)[a];
    float b[4], areaA; bool valid;
    predbox(A4, d, b, &areaA, &valid);
    int gid = 0;
    if (valid) {
        float best = -1.0f;
#pragma unroll 4
        for (int m = 0; m < MG; m++) {
            float4 g = sg[m];
            float ag = __fmul_rn(__fadd_rn(__fsub_rn(g.z, g.x), 1.0f),
                                 __fadd_rn(__fsub_rn(g.w, g.y), 1.0f));
            float iw = fmaxf(__fadd_rn(__fsub_rn(fminf(b[2], g.z), fmaxf(b[0], g.x)), 1.0f), 0.0f);
            float ih = fmaxf(__fadd_rn(__fsub_rn(fminf(b[3], g.w), fmaxf(b[1], g.y)), 1.0f), 0.0f);
            float inter = __fmul_rn(iw, ih);
            float ov = iou_div(inter, areaA, ag);
            if (ov > best) { best = ov; gid = m; }
        }
    }
    float4 G = sg[gid];
    float aw = A4.z - A4.x + 1.0f, ah = A4.w - A4.y + 1.0f;
    float acx = A4.x + 0.5f * aw, acy = A4.y + 0.5f * ah;
    float gw = G.z - G.x + 1.0f, gh = G.w - G.y + 1.0f;
    float gcx = G.x + 0.5f * gw, gcy = G.y + 0.5f * gh;
    out[n * TOTAL_K + p] = (float)a;
    out[NI * TOTAL_K + n * TOTAL_K + p] = fg ? 1.0f : 0.0f;
    float* c = &out[2 * NI * TOTAL_K + (unsigned)(n * TOTAL_K + p) * 4u];
    c[0] = (gcx - acx) / aw;
    c[1] = (gcy - acy) / ah;
    c[2] = logf(gw / aw);
    c[3] = logf(gh / ah);
}

__global__ void __launch_bounds__(512) k_out(const float* __restrict__ anchors,
                                             const float* __restrict__ gtb,
                                             const float* __restrict__ deltas,
                                             const float* __restrict__ rs,
                                             float* __restrict__ out) {
    const int n = blockIdx.x;
    const int tid = threadIdx.x;
    __shared__ float4 sg[MG];
    __shared__ unsigned slist[TOTAL_K];
    __shared__ unsigned scnt;
    if (tid < MG) sg[tid] = ((const float4*)gtb)[n * MG + tid];
    if (tid == 0) scnt = 0;
    const unsigned long long cutF = g_cut[n * 2 + 1];
    const unsigned long long cutB = g_cut[n * 2 + 0];
    __syncthreads();

    // stripe scan: thread t covers a' in [t*72, t*72+72), u64 label loads
    const unsigned long long* lp =
        (const unsigned long long*)(g_label + (size_t)n * AN);
#pragma unroll
    for (int i = 0; i < 9; i++) {
        unsigned long long v = lp[tid * 9 + i];
#pragma unroll
        for (int j = 0; j < 8; j++) {
            signed char lab = (signed char)((v >> (j * 8)) & 0xFF);
            if (lab < 0) continue;
            int ap = (tid * 9 + i) * 8 + j;
            int a = (ap & (NPOS - 1)) * NTYPE + (ap >> 12);
            unsigned long long k = keyf(rs[n * AN + a], a);
            bool kept = (lab == 1) ? (k >= cutF) : (k >= cutB);
            if (kept) {
                unsigned slot = atomicAdd(&scnt, 1u);
                if (slot < TOTAL_K)
                    slist[slot] = (unsigned)a | ((lab == 1) ? 0x80000000u : 0u);
            }
        }
    }
    __syncthreads();
    unsigned cnt = scnt < TOTAL_K ? scnt : TOTAL_K;

    // rank-sort by anchor index ascending (entries distinct)
    if (tid < (int)cnt) {
        unsigned e = slist[tid];
        unsigned ai = e & 0x7FFFFFFFu;
        unsigned rank = 0;
        for (unsigned j = 0; j < cnt; j++)
            rank += ((slist[j] & 0x7FFFFFFFu) < ai);
        write_out(out, n, rank, (int)ai, (e & 0x80000000u) != 0, sg,
                  anchors, deltas + (size_t)n * AN * 4);
    }

    // pad tail with anchor 0 (matches reference scatter-zeros semantics)
    if ((unsigned)tid >= cnt && tid < TOTAL_K) {
        signed char lab0 = g_label[(size_t)n * AN + 0];   // a'=0 <-> a=0
        bool fg0 = (lab0 == 1) && (keyf(rs[n * AN + 0], 0) >= cutF);
        write_out(out, n, (unsigned)tid, 0, fg0, sg,
                  anchors, deltas + (size_t)n * AN * 4);
    }
}

// ----- launch ---------------------------------------------------------------
extern "C" void kernel_launch(void* const* d_in, const int* in_sizes, int n_in,
                              void* d_out, int out_size) {
    const float *anchors = nullptr, *gtb = nullptr, *deltas = nullptr, *rsc = nullptr;
    for (int i = 0; i < n_in; i++) {
        int s = in_sizes[i];
        if (s == AN * 4)           anchors = (const float*)d_in[i];
        else if (s == NI * MG * 4) gtb     = (const float*)d_in[i];
        else if (s == NI * AN * 4) deltas  = (const float*)d_in[i];
        else if (s == NI * AN)     rsc     = (const float*)d_in[i];
    }
    float* out = (float*)d_out;

    k_init<<<(NI * 2 * NBUCK + 255) / 256, 256>>>();
    dim3 g1(NPOS / PCHUNK, NI);   // (16, 32)
    k_pass1<<<g1, PCHUNK>>>(anchors, gtb, deltas);
    k_pass2<<<g1, PCHUNK>>>(anchors, gtb, deltas, rsc);
    k_select<<<NI, 256>>>(rsc);
    k_out<<<NI, 512>>>(anchors, gtb, deltas, rsc, out);
}

// round 3
// speedup vs baseline: 5.4351x; 1.2105x over previous
#include <cuda_runtime.h>

// ---------------------------------------------------------------------------
// AnchorRefine R3:
//  - pass1: warp gt-skip mask (ballot), per-gt max, amax
//  - pass2: a_box upgrade + final labels + key append into 256 coarse r-buckets
//  - finish: bucket-walk cutoff + rank-select + ordered compaction + outputs
// Output f32 buffer 49152: [0,8192) idx, [8192,16384) fg, [16384,49152) coeff.
// Scratch layout a' = type*4096 + pos (coalesced); real a = pos*9 + type.
// ---------------------------------------------------------------------------

#define AN      36864
#define NPOS    4096
#define NTYPE   9
#define NI      32
#define MG      32
#define TOTAL_K 256
#define MAXFG   128
#define POS_T   0.7f
#define NEG_T   0.3f
#define IMGSZ   1024.0f
#define NBUCKC  256
#define CAPC    512
#define PCHUNK  256

// ----- device scratch ------------------------------------------------------
__device__ __align__(16) float              g_amax [NI * AN];      // [n][a']
__device__ __align__(16) signed char        g_label[NI * AN];      // [n][a'] final
__device__ __align__(16) unsigned long long g_key  [NI * AN];      // [n][a'] (lab>=0)
__device__ unsigned                         g_pgm  [NI * MG];
__device__ unsigned                         g_bcnt [NI * 2 * NBUCKC];
__device__ unsigned long long               g_blist[(size_t)NI * 2 * NBUCKC * CAPC];

// ----- helpers -------------------------------------------------------------
__device__ __forceinline__ unsigned encf(float f) {
    unsigned b = __float_as_uint(f);
    return (b & 0x80000000u) ? ~b : (b | 0x80000000u);
}
__device__ __forceinline__ float decf(unsigned u) {
    unsigned b = (u & 0x80000000u) ? (u ^ 0x80000000u) : ~u;
    return __uint_as_float(b);
}
__device__ __forceinline__ int bucketc(float r) {
    int b = (int)(r * 256.0f);
    return b < 0 ? 0 : (b > 255 ? 255 : b);
}
__device__ __forceinline__ unsigned long long keyf(float r, int a) {
    return (((unsigned long long)__float_as_uint(r)) << 32)
         | (unsigned)(0xFFFFFFFFu - (unsigned)a);
}

// bbox_transform, exact reference op order, no FMA contraction.
__device__ __forceinline__ void predbox(float4 an, float4 d, float* b,
                                        float* areaA, bool* valid) {
    float w  = __fadd_rn(__fsub_rn(an.z, an.x), 1.0f);
    float h  = __fadd_rn(__fsub_rn(an.w, an.y), 1.0f);
    float cx = __fadd_rn(an.x, __fmul_rn(0.5f, w));
    float cy = __fadd_rn(an.y, __fmul_rn(0.5f, h));
    float pcx = __fadd_rn(__fmul_rn(d.x, w), cx);
    float pcy = __fadd_rn(__fmul_rn(d.y, h), cy);
    float pw  = __fmul_rn(expf(d.z), w);
    float ph  = __fmul_rn(expf(d.w), h);
    b[0] = __fsub_rn(pcx, __fmul_rn(0.5f, pw));
    b[1] = __fsub_rn(pcy, __fmul_rn(0.5f, ph));
    b[2] = __fadd_rn(pcx, __fmul_rn(0.5f, pw));
    b[3] = __fadd_rn(pcy, __fmul_rn(0.5f, ph));
    *areaA = __fmul_rn(__fadd_rn(__fsub_rn(b[2], b[0]), 1.0f),
                       __fadd_rn(__fsub_rn(b[3], b[1]), 1.0f));
    *valid = (b[0] >= 0.0f) && (b[1] >= 0.0f) && (b[2] < IMGSZ) && (b[3] < IMGSZ);
}

__device__ __forceinline__ float iou_div(float inter, float areaA, float ag) {
    return __fdiv_rn(inter, __fsub_rn(__fadd_rn(areaA, ag), inter));
}

// ----- K0: init ------------------------------------------------------------
__global__ void k_init() {
    int i = blockIdx.x * blockDim.x + threadIdx.x;
    if (i < NI * MG)             g_pgm[i]  = 0x407FFFFFu;   // encf(-1.0f)
    if (i < NI * 2 * NBUCKC)     g_bcnt[i] = 0u;
}

// ----- K1: pred boxes, anchor_max, per-gt max ------------------------------
__global__ void __launch_bounds__(256) k_pass1(const float* __restrict__ anchors,
                                               const float* __restrict__ gtb,
                                               const float* __restrict__ deltas) {
    const int n = blockIdx.y;
    const int tid = threadIdx.x;
    const int p = blockIdx.x * PCHUNK + tid;
    const int lane = tid & 31;
    __shared__ float4 sg[MG];
    __shared__ float  sga[MG];
    __shared__ float  sred[8][MG];
    if (tid < MG) {
        float4 g = ((const float4*)gtb)[n * MG + tid];
        sg[tid] = g;
        sga[tid] = __fmul_rn(__fadd_rn(__fsub_rn(g.z, g.x), 1.0f),
                             __fadd_rn(__fsub_rn(g.w, g.y), 1.0f));
    }
    __syncthreads();
    const float4 gl = sg[lane];   // gt box owned by this lane for mask tests

    float lmax[MG];
#pragma unroll
    for (int m = 0; m < MG; m++) lmax[m] = -1.0f;
    bool anyv = false;

    for (int type = 0; type < NTYPE; type++) {
        const int a  = p * NTYPE + type;
        const int ap = type * NPOS + p;
        float4 an = ((const float4*)anchors)[a];
        float4 d  = ((const float4*)deltas)[n * AN + a];
        float b[4], areaA; bool valid;
        predbox(an, d, b, &areaA, &valid);

        // warp y-extent over VALID lanes (sentinels for invalid)
        float b1s = valid ? b[1] :  1e30f;
        float b3s = valid ? b[3] : -1e30f;
#pragma unroll
        for (int off = 16; off; off >>= 1) {
            b1s = fminf(b1s, __shfl_xor_sync(0xFFFFFFFFu, b1s, off));
            b3s = fmaxf(b3s, __shfl_xor_sync(0xFFFFFFFFu, b3s, off));
        }
        // lane m tests feasibility of gt m against the warp's y-extent.
        // Conservative (monotone rounding): skip only if surely no overlap.
        bool poss = (__fadd_rn(__fsub_rn(gl.w, b1s), 1.0f) > 0.0f) &&
                    (__fadd_rn(__fsub_rn(b3s, gl.y), 1.0f) > 0.0f);
        unsigned mask = __ballot_sync(0xFFFFFFFFu, poss);

        float amax = -1.0f;
        if (valid) {
            anyv = true;
            amax = 0.0f;
#pragma unroll
            for (int m = 0; m < MG; m++) {
                if (mask & (1u << m)) {
                    float4 g = sg[m];
                    float iw = __fadd_rn(__fsub_rn(fminf(b[2], g.z), fmaxf(b[0], g.x)), 1.0f);
                    float ih = __fadd_rn(__fsub_rn(fminf(b[3], g.w), fmaxf(b[1], g.y)), 1.0f);
                    if (iw > 0.0f && ih > 0.0f) {
                        float inter = __fmul_rn(iw, ih);
                        float ov = iou_div(inter, areaA, sga[m]);
                        amax = fmaxf(amax, ov);
                        lmax[m] = fmaxf(lmax[m], ov);
                    }
                }
            }
        }
        g_amax[n * AN + ap] = amax;
    }

    const int wid = tid >> 5;
#pragma unroll
    for (int m = 0; m < MG; m++) {
        float v = lmax[m];
        for (int off = 16; off; off >>= 1)
            v = fmaxf(v, __shfl_xor_sync(0xFFFFFFFFu, v, off));
        if (lane == 0) sred[wid][m] = v;
    }
    int anyv_all = __syncthreads_or(anyv ? 1 : 0);
    if (tid < MG) {
        float v = sred[0][tid];
#pragma unroll
        for (int w = 1; w < 8; w++) v = fmaxf(v, sred[w][tid]);
        if (anyv_all) v = fmaxf(v, 0.0f);   // valid anchors contribute ov>=0
        atomicMax(&g_pgm[n * MG + tid], encf(v));
    }
}

// ----- K2: a_box upgrade + final labels + bucket key append ----------------
__global__ void __launch_bounds__(256) k_pass2(const float* __restrict__ anchors,
                                               const float* __restrict__ gtb,
                                               const float* __restrict__ deltas,
                                               const float* __restrict__ rs) {
    const int n = blockIdx.y;
    const int tid = threadIdx.x;
    const int p = blockIdx.x * PCHUNK + tid;
    __shared__ float4 sg[MG];
    __shared__ float  sga[MG];
    __shared__ float  spgm[MG];
    __shared__ float  sminp;
    if (tid < MG) {
        float4 g = ((const float4*)gtb)[n * MG + tid];
        sg[tid] = g;
        sga[tid] = __fmul_rn(__fadd_rn(__fsub_rn(g.z, g.x), 1.0f),
                             __fadd_rn(__fsub_rn(g.w, g.y), 1.0f));
        spgm[tid] = decf(g_pgm[n * MG + tid]);
    }
    __syncthreads();
    if (tid == 0) {
        float mn = spgm[0];
        for (int m = 1; m < MG; m++) mn = fminf(mn, spgm[m]);
        sminp = mn;
    }
    __syncthreads();

    for (int type = 0; type < NTYPE; type++) {
        const int a  = p * NTYPE + type;
        const int ap = type * NPOS + p;
        float amax = g_amax[n * AN + ap];
        signed char lab = (amax >= POS_T) ? 1
                        : ((amax >= 0.0f && amax < NEG_T) ? 0 : -1);
        if (lab != 1 && amax >= 0.0f && amax >= sminp) {  // a_box necessary cond
            float4 an = ((const float4*)anchors)[a];
            float4 d  = ((const float4*)deltas)[n * AN + a];
            float b[4], areaA; bool valid;
            predbox(an, d, b, &areaA, &valid);
            bool abox = false;
#pragma unroll 4
            for (int m = 0; m < MG; m++) {
                float pm = spgm[m];
                if (pm <= amax) {
                    float4 g = sg[m];
                    float iw = __fadd_rn(__fsub_rn(fminf(b[2], g.z), fmaxf(b[0], g.x)), 1.0f);
                    float ih = __fadd_rn(__fsub_rn(fminf(b[3], g.w), fmaxf(b[1], g.y)), 1.0f);
                    if (iw > 0.0f && ih > 0.0f) {
                        float inter = __fmul_rn(iw, ih);
                        float ov = iou_div(inter, areaA, sga[m]);
                        abox |= (ov == pm);
                    } else {
                        abox |= (pm == 0.0f);
                    }
                }
            }
            if (abox) lab = 1;
        }
        g_label[n * AN + ap] = lab;
        if (lab >= 0) {
            float r = rs[n * AN + a];
            unsigned long long k = keyf(r, a);
            g_key[n * AN + ap] = k;
            int bk = bucketc(r);
            unsigned base = (unsigned)(n * 2 + lab) * NBUCKC + bk;
            unsigned q = atomicAdd(&g_bcnt[base], 1u);
            if (q < CAPC) g_blist[(size_t)base * CAPC + q] = k;
        }
    }
}

// ----- K3: cutoffs + ordered compaction + outputs --------------------------
__device__ __forceinline__ void write_out(float* out, int n, unsigned p, int a,
                                          bool fg, const float4* sg,
                                          const float* anchors,
                                          const float* deltasImg) {
    float4 A4 = ((const float4*)anchors)[a];
    float4 d  = ((const float4*)deltasImg)[a];
    float b[4], areaA; bool valid;
    predbox(A4, d, b, &areaA, &valid);
    int gid = 0;
    if (valid) {
        float best = -1.0f;
#pragma unroll 4
        for (int m = 0; m < MG; m++) {
            float4 g = sg[m];
            float ag = __fmul_rn(__fadd_rn(__fsub_rn(g.z, g.x), 1.0f),
                                 __fadd_rn(__fsub_rn(g.w, g.y), 1.0f));
            float iw = fmaxf(__fadd_rn(__fsub_rn(fminf(b[2], g.z), fmaxf(b[0], g.x)), 1.0f), 0.0f);
            float ih = fmaxf(__fadd_rn(__fsub_rn(fminf(b[3], g.w), fmaxf(b[1], g.y)), 1.0f), 0.0f);
            float inter = __fmul_rn(iw, ih);
            float ov = iou_div(inter, areaA, ag);
            if (ov > best) { best = ov; gid = m; }
        }
    }
    float4 G = sg[gid];
    float aw = A4.z - A4.x + 1.0f, ah = A4.w - A4.y + 1.0f;
    float acx = A4.x + 0.5f * aw, acy = A4.y + 0.5f * ah;
    float gw = G.z - G.x + 1.0f, gh = G.w - G.y + 1.0f;
    float gcx = G.x + 0.5f * gw, gcy = G.y + 0.5f * gh;
    out[n * TOTAL_K + p] = (float)a;
    out[NI * TOTAL_K + n * TOTAL_K + p] = fg ? 1.0f : 0.0f;
    float* c = &out[2 * NI * TOTAL_K + (unsigned)(n * TOTAL_K + p) * 4u];
    c[0] = (gcx - acx) / aw;
    c[1] = (gcy - acy) / ah;
    c[2] = logf(gw / aw);
    c[3] = logf(gh / ah);
}

__global__ void __launch_bounds__(512) k_finish(const float* __restrict__ anchors,
                                                const float* __restrict__ gtb,
                                                const float* __restrict__ deltas,
                                                float* __restrict__ out) {
    const int n = blockIdx.x;
    const int tid = threadIdx.x;
    __shared__ float4 sg[MG];
    __shared__ unsigned scF[NBUCKC], scB[NBUCKC];
    __shared__ unsigned long long kF[CAPC], kB[CAPC];
    __shared__ unsigned long long scutF, scutB;
    __shared__ int sbF, sbB;
    __shared__ unsigned sneedF, sneedB, sLF, sLB;
    __shared__ unsigned slist[TOTAL_K];
    __shared__ unsigned scnt;

    if (tid < MG) sg[tid] = ((const float4*)gtb)[n * MG + tid];
    if (tid < NBUCKC) {
        scF[tid] = g_bcnt[(unsigned)(n * 2 + 1) * NBUCKC + tid];
        scB[tid] = g_bcnt[(unsigned)(n * 2 + 0) * NBUCKC + tid];
    }
    if (tid == 0) { scutF = 0ull; scutB = 0ull; sbF = -1; sbB = -1;
                    scnt = 0; sLF = 0; sLB = 0; }
    __syncthreads();

    if (tid == 0) {
        unsigned totF = 0, totB = 0;
        for (int b = 0; b < NBUCKC; b++) { totF += scF[b]; totB += scB[b]; }
        unsigned keptfg = totF < MAXFG ? totF : MAXFG;
        unsigned quota = TOTAL_K - keptfg;
        if (totF > MAXFG) {
            unsigned cum = 0;
            for (int b = NBUCKC - 1; b >= 0; b--) {
                if (cum + scF[b] >= MAXFG) {
                    sbF = b; sneedF = MAXFG - cum;
                    sLF = scF[b] < CAPC ? scF[b] : CAPC;
                    break;
                }
                cum += scF[b];
            }
        }
        if (totB > quota) {
            unsigned cum = 0;
            for (int b = NBUCKC - 1; b >= 0; b--) {
                if (cum + scB[b] >= quota) {
                    sbB = b; sneedB = quota - cum;
                    sLB = scB[b] < CAPC ? scB[b] : CAPC;
                    break;
                }
                cum += scB[b];
            }
        }
    }
    __syncthreads();

    if (sbF >= 0 && tid < (int)sLF)
        kF[tid] = g_blist[((size_t)((n * 2 + 1) * NBUCKC + sbF)) * CAPC + tid];
    if (sbB >= 0 && tid < (int)sLB)
        kB[tid] = g_blist[((size_t)((n * 2 + 0) * NBUCKC + sbB)) * CAPC + tid];
    __syncthreads();

    if (sbF >= 0 && tid < (int)sLF) {
        unsigned long long k = kF[tid];
        unsigned c = 0;
        for (unsigned j = 0; j < sLF; j++) c += (kF[j] > k);
        if (c == sneedF - 1) scutF = k;
    }
    if (sbB >= 0 && tid < (int)sLB) {
        unsigned long long k = kB[tid];
        unsigned c = 0;
        for (unsigned j = 0; j < sLB; j++) c += (kB[j] > k);
        if (c == sneedB - 1) scutB = k;
    }
    __syncthreads();
    const unsigned long long cutF = (sbF >= 0) ? scutF : 0ull;
    const unsigned long long cutB = (sbB >= 0) ? scutB : 0ull;

    // compaction scan over packed labels
    const unsigned long long* lp =
        (const unsigned long long*)(g_label + (size_t)n * AN);
#pragma unroll
    for (int i = 0; i < 9; i++) {
        unsigned long long v = lp[tid * 9 + i];
        if (v == 0xFFFFFFFFFFFFFFFFull) continue;   // all ignore
#pragma unroll
        for (int j = 0; j < 8; j++) {
            signed char lab = (signed char)((v >> (j * 8)) & 0xFF);
            if (lab < 0) continue;
            int ap = (tid * 9 + i) * 8 + j;
            unsigned long long k = g_key[(size_t)n * AN + ap];
            bool kept = (lab == 1) ? (k >= cutF) : (k >= cutB);
            if (kept) {
                int a = (ap & (NPOS - 1)) * NTYPE + (ap >> 12);
                unsigned slot = atomicAdd(&scnt, 1u);
                if (slot < TOTAL_K)
                    slist[slot] = (unsigned)a | ((lab == 1) ? 0x80000000u : 0u);
            }
        }
    }
    __syncthreads();
    unsigned cnt = scnt < TOTAL_K ? scnt : TOTAL_K;

    if (tid < (int)cnt) {
        unsigned e = slist[tid];
        unsigned ai = e & 0x7FFFFFFFu;
        unsigned rank = 0;
        for (unsigned j = 0; j < cnt; j++)
            rank += ((slist[j] & 0x7FFFFFFFu) < ai);
        write_out(out, n, rank, (int)ai, (e & 0x80000000u) != 0, sg,
                  anchors, deltas + (size_t)n * AN * 4);
    }
    if ((unsigned)tid >= cnt && tid < TOTAL_K) {
        signed char lab0 = g_label[(size_t)n * AN + 0];   // a'=0 <-> a=0
        bool fg0 = false;
        if (lab0 == 1) fg0 = (g_key[(size_t)n * AN + 0] >= cutF);
        write_out(out, n, (unsigned)tid, 0, fg0, sg,
                  anchors, deltas + (size_t)n * AN * 4);
    }
}

// ----- launch ---------------------------------------------------------------
extern "C" void kernel_launch(void* const* d_in, const int* in_sizes, int n_in,
                              void* d_out, int out_size) {
    const float *anchors = nullptr, *gtb = nullptr, *deltas = nullptr, *rsc = nullptr;
    for (int i = 0; i < n_in; i++) {
        int s = in_sizes[i];
        if (s == AN * 4)           anchors = (const float*)d_in[i];
        else if (s == NI * MG * 4) gtb     = (const float*)d_in[i];
        else if (s == NI * AN * 4) deltas  = (const float*)d_in[i];
        else if (s == NI * AN)     rsc     = (const float*)d_in[i];
    }
    float* out = (float*)d_out;

    k_init<<<(NI * 2 * NBUCKC + 255) / 256, 256>>>();
    dim3 g1(NPOS / PCHUNK, NI);   // (16, 32)
    k_pass1<<<g1, PCHUNK>>>(anchors, gtb, deltas);
    k_pass2<<<g1, PCHUNK>>>(anchors, gtb, deltas, rsc);
    k_finish<<<NI, 512>>>(anchors, gtb, deltas, out);
}

// round 4
// speedup vs baseline: 6.7341x; 1.2390x over previous
#include <cuda_runtime.h>

// ---------------------------------------------------------------------------
// AnchorRefine R4:
//  - pass1: 2D warp tiles (8x4 positions) + xy gt-feasibility ballot mask
//  - pass2: a_box upgrade + final labels + key append into 256 coarse r-buckets
//  - finish: enumerate kept set directly from bucket lists (no label rescan),
//            parallel suffix scan, rank-sort, outputs
// Output f32 buffer 49152: [0,8192) idx, [8192,16384) fg, [16384,49152) coeff.
// Scratch layout a' = type*4096 + pos; real anchor index a = pos*9 + type.
// Key = (r_bits<<32) | ~a  -> reproduces rank_desc order; a = ~(u32)key.
// ---------------------------------------------------------------------------

#define AN      36864
#define NPOS    4096
#define NTYPE   9
#define NI      32
#define MG      32
#define TOTAL_K 256
#define MAXFG   128
#define POS_T   0.7f
#define NEG_T   0.3f
#define IMGSZ   1024.0f
#define NBUCKC  256
#define CAPC    512
#define PCHUNK  256

// ----- device scratch ------------------------------------------------------
__device__ __align__(16) float       g_amax [NI * AN];   // [n][a']
__device__ __align__(16) signed char g_label[NI * AN];   // [n][a'] final
__device__ unsigned                  g_pgm  [NI * MG];   // ordered-encoded per-gt max
__device__ unsigned                  g_bcnt [NI * 2 * NBUCKC];
__device__ unsigned long long        g_blist[(size_t)NI * 2 * NBUCKC * CAPC];

// ----- helpers -------------------------------------------------------------
__device__ __forceinline__ unsigned encf(float f) {
    unsigned b = __float_as_uint(f);
    return (b & 0x80000000u) ? ~b : (b | 0x80000000u);
}
__device__ __forceinline__ float decf(unsigned u) {
    unsigned b = (u & 0x80000000u) ? (u ^ 0x80000000u) : ~u;
    return __uint_as_float(b);
}
__device__ __forceinline__ int bucketc(float r) {
    int b = (int)(r * 256.0f);
    return b < 0 ? 0 : (b > 255 ? 255 : b);
}
__device__ __forceinline__ unsigned long long keyf(float r, int a) {
    return (((unsigned long long)__float_as_uint(r)) << 32)
         | (unsigned)(0xFFFFFFFFu - (unsigned)a);
}

// bbox_transform, exact reference op order, no FMA contraction.
__device__ __forceinline__ void predbox(float4 an, float4 d, float* b,
                                        float* areaA, bool* valid) {
    float w  = __fadd_rn(__fsub_rn(an.z, an.x), 1.0f);
    float h  = __fadd_rn(__fsub_rn(an.w, an.y), 1.0f);
    float cx = __fadd_rn(an.x, __fmul_rn(0.5f, w));
    float cy = __fadd_rn(an.y, __fmul_rn(0.5f, h));
    float pcx = __fadd_rn(__fmul_rn(d.x, w), cx);
    float pcy = __fadd_rn(__fmul_rn(d.y, h), cy);
    float pw  = __fmul_rn(expf(d.z), w);
    float ph  = __fmul_rn(expf(d.w), h);
    b[0] = __fsub_rn(pcx, __fmul_rn(0.5f, pw));
    b[1] = __fsub_rn(pcy, __fmul_rn(0.5f, ph));
    b[2] = __fadd_rn(pcx, __fmul_rn(0.5f, pw));
    b[3] = __fadd_rn(pcy, __fmul_rn(0.5f, ph));
    *areaA = __fmul_rn(__fadd_rn(__fsub_rn(b[2], b[0]), 1.0f),
                       __fadd_rn(__fsub_rn(b[3], b[1]), 1.0f));
    *valid = (b[0] >= 0.0f) && (b[1] >= 0.0f) && (b[2] < IMGSZ) && (b[3] < IMGSZ);
}

__device__ __forceinline__ float iou_div(float inter, float areaA, float ag) {
    return __fdiv_rn(inter, __fsub_rn(__fadd_rn(areaA, ag), inter));
}

// ----- K0: init ------------------------------------------------------------
__global__ void k_init() {
    int i = blockIdx.x * blockDim.x + threadIdx.x;
    if (i < NI * MG)         g_pgm[i]  = 0x407FFFFFu;   // encf(-1.0f)
    if (i < NI * 2 * NBUCKC) g_bcnt[i] = 0u;
}

// ----- K1: pred boxes, anchor_max, per-gt max ------------------------------
__global__ void __launch_bounds__(256) k_pass1(const float* __restrict__ anchors,
                                               const float* __restrict__ gtb,
                                               const float* __restrict__ deltas) {
    const int n = blockIdx.y;
    const int tid = threadIdx.x;
    const int lane = tid & 31;
    const int w = tid >> 5;
    // 2D warp tile: warp covers 8 cols x 4 rows of positions
    const int px = ((w & 7) << 3) + (lane & 7);             // 0..63
    const int py = (blockIdx.x << 2) + (lane >> 3);         // 0..63
    const int p  = (py << 6) + px;

    __shared__ float4 sg[MG];
    __shared__ float  sga[MG];
    __shared__ float  sred[8][MG];
    if (tid < MG) {
        float4 g = ((const float4*)gtb)[n * MG + tid];
        sg[tid] = g;
        sga[tid] = __fmul_rn(__fadd_rn(__fsub_rn(g.z, g.x), 1.0f),
                             __fadd_rn(__fsub_rn(g.w, g.y), 1.0f));
    }
    __syncthreads();
    const float4 gl = sg[lane];   // gt box owned by this lane for mask tests

    float lmax[MG];
#pragma unroll
    for (int m = 0; m < MG; m++) lmax[m] = -1.0f;
    bool anyv = false;

    for (int type = 0; type < NTYPE; type++) {
        const int a  = p * NTYPE + type;
        const int ap = type * NPOS + p;
        float4 an = ((const float4*)anchors)[a];
        float4 d  = ((const float4*)deltas)[n * AN + a];
        float b[4], areaA; bool valid;
        predbox(an, d, b, &areaA, &valid);

        // warp xy-extent over VALID lanes (sentinels for invalid)
        float b0s = valid ? b[0] :  1e30f;
        float b1s = valid ? b[1] :  1e30f;
        float b2s = valid ? b[2] : -1e30f;
        float b3s = valid ? b[3] : -1e30f;
#pragma unroll
        for (int off = 16; off; off >>= 1) {
            b0s = fminf(b0s, __shfl_xor_sync(0xFFFFFFFFu, b0s, off));
            b1s = fminf(b1s, __shfl_xor_sync(0xFFFFFFFFu, b1s, off));
            b2s = fmaxf(b2s, __shfl_xor_sync(0xFFFFFFFFu, b2s, off));
            b3s = fmaxf(b3s, __shfl_xor_sync(0xFFFFFFFFu, b3s, off));
        }
        // lane m: conservative feasibility of gt m vs warp extent
        bool poss = (__fadd_rn(__fsub_rn(gl.z, b0s), 1.0f) > 0.0f) &&
                    (__fadd_rn(__fsub_rn(b2s, gl.x), 1.0f) > 0.0f) &&
                    (__fadd_rn(__fsub_rn(gl.w, b1s), 1.0f) > 0.0f) &&
                    (__fadd_rn(__fsub_rn(b3s, gl.y), 1.0f) > 0.0f);
        unsigned mask = __ballot_sync(0xFFFFFFFFu, poss);

        float amax = -1.0f;
        if (valid) {
            anyv = true;
            amax = 0.0f;
#pragma unroll
            for (int m = 0; m < MG; m++) {
                if (mask & (1u << m)) {
                    float4 g = sg[m];
                    float iw = __fadd_rn(__fsub_rn(fminf(b[2], g.z), fmaxf(b[0], g.x)), 1.0f);
                    float ih = __fadd_rn(__fsub_rn(fminf(b[3], g.w), fmaxf(b[1], g.y)), 1.0f);
                    if (iw > 0.0f && ih > 0.0f) {
                        float inter = __fmul_rn(iw, ih);
                        float ov = iou_div(inter, areaA, sga[m]);
                        amax = fmaxf(amax, ov);
                        lmax[m] = fmaxf(lmax[m], ov);
                    }
                }
            }
        }
        g_amax[n * AN + ap] = amax;
    }

#pragma unroll
    for (int m = 0; m < MG; m++) {
        float v = lmax[m];
        for (int off = 16; off; off >>= 1)
            v = fmaxf(v, __shfl_xor_sync(0xFFFFFFFFu, v, off));
        if (lane == 0) sred[w][m] = v;
    }
    int anyv_all = __syncthreads_or(anyv ? 1 : 0);
    if (tid < MG) {
        float v = sred[0][tid];
#pragma unroll
        for (int ww = 1; ww < 8; ww++) v = fmaxf(v, sred[ww][tid]);
        if (anyv_all) v = fmaxf(v, 0.0f);   // valid anchors contribute ov >= 0
        atomicMax(&g_pgm[n * MG + tid], encf(v));
    }
}

// ----- K2: a_box upgrade + final labels + bucket key append ----------------
__global__ void __launch_bounds__(256) k_pass2(const float* __restrict__ anchors,
                                               const float* __restrict__ gtb,
                                               const float* __restrict__ deltas,
                                               const float* __restrict__ rs) {
    const int n = blockIdx.y;
    const int tid = threadIdx.x;
    const int p = blockIdx.x * PCHUNK + tid;
    __shared__ float4 sg[MG];
    __shared__ float  sga[MG];
    __shared__ float  spgm[MG];
    __shared__ float  sminp;
    if (tid < MG) {
        float4 g = ((const float4*)gtb)[n * MG + tid];
        sg[tid] = g;
        sga[tid] = __fmul_rn(__fadd_rn(__fsub_rn(g.z, g.x), 1.0f),
                             __fadd_rn(__fsub_rn(g.w, g.y), 1.0f));
        spgm[tid] = decf(g_pgm[n * MG + tid]);
    }
    __syncthreads();
    if (tid == 0) {
        float mn = spgm[0];
        for (int m = 1; m < MG; m++) mn = fminf(mn, spgm[m]);
        sminp = mn;
    }
    __syncthreads();

    for (int type = 0; type < NTYPE; type++) {
        const int a  = p * NTYPE + type;
        const int ap = type * NPOS + p;
        float amax = g_amax[n * AN + ap];
        signed char lab = (amax >= POS_T) ? 1
                        : ((amax >= 0.0f && amax < NEG_T) ? 0 : -1);
        if (lab != 1 && amax >= 0.0f && amax >= sminp) {  // a_box necessary cond
            float4 an = ((const float4*)anchors)[a];
            float4 d  = ((const float4*)deltas)[n * AN + a];
            float b[4], areaA; bool valid;
            predbox(an, d, b, &areaA, &valid);
            bool abox = false;
#pragma unroll 4
            for (int m = 0; m < MG; m++) {
                float pm = spgm[m];
                if (pm <= amax) {
                    float4 g = sg[m];
                    float iw = __fadd_rn(__fsub_rn(fminf(b[2], g.z), fmaxf(b[0], g.x)), 1.0f);
                    float ih = __fadd_rn(__fsub_rn(fminf(b[3], g.w), fmaxf(b[1], g.y)), 1.0f);
                    if (iw > 0.0f && ih > 0.0f) {
                        float inter = __fmul_rn(iw, ih);
                        float ov = iou_div(inter, areaA, sga[m]);
                        abox |= (ov == pm);
                    } else {
                        abox |= (pm == 0.0f);
                    }
                }
            }
            if (abox) lab = 1;
        }
        g_label[n * AN + ap] = lab;
        if (lab >= 0) {
            float r = rs[n * AN + a];
            int bk = bucketc(r);
            unsigned base = (unsigned)(n * 2 + lab) * NBUCKC + bk;
            unsigned q = atomicAdd(&g_bcnt[base], 1u);
            if (q < CAPC) g_blist[(size_t)base * CAPC + q] = keyf(r, a);
        }
    }
}

// ----- K3: kept-set enumeration from bucket lists + outputs ----------------
__device__ __forceinline__ void write_out(float* out, int n, unsigned p, int a,
                                          bool fg, const float4* sg,
                                          const float* anchors,
                                          const float* deltasImg) {
    float4 A4 = ((const float4*)anchors)[a];
    float4 d  = ((const float4*)deltasImg)[a];
    float b[4], areaA; bool valid;
    predbox(A4, d, b, &areaA, &valid);
    int gid = 0;
    if (valid) {
        float best = -1.0f;
#pragma unroll 4
        for (int m = 0; m < MG; m++) {
            float4 g = sg[m];
            float ag = __fmul_rn(__fadd_rn(__fsub_rn(g.z, g.x), 1.0f),
                                 __fadd_rn(__fsub_rn(g.w, g.y), 1.0f));
            float iw = fmaxf(__fadd_rn(__fsub_rn(fminf(b[2], g.z), fmaxf(b[0], g.x)), 1.0f), 0.0f);
            float ih = fmaxf(__fadd_rn(__fsub_rn(fminf(b[3], g.w), fmaxf(b[1], g.y)), 1.0f), 0.0f);
            float inter = __fmul_rn(iw, ih);
            float ov = iou_div(inter, areaA, ag);
            if (ov > best) { best = ov; gid = m; }
        }
    }
    float4 G = sg[gid];
    float aw = A4.z - A4.x + 1.0f, ah = A4.w - A4.y + 1.0f;
    float acx = A4.x + 0.5f * aw, acy = A4.y + 0.5f * ah;
    float gw = G.z - G.x + 1.0f, gh = G.w - G.y + 1.0f;
    float gcx = G.x + 0.5f * gw, gcy = G.y + 0.5f * gh;
    out[n * TOTAL_K + p] = (float)a;
    out[NI * TOTAL_K + n * TOTAL_K + p] = fg ? 1.0f : 0.0f;
    float* c = &out[2 * NI * TOTAL_K + (unsigned)(n * TOTAL_K + p) * 4u];
    c[0] = (gcx - acx) / aw;
    c[1] = (gcy - acy) / ah;
    c[2] = logf(gw / aw);
    c[3] = logf(gh / ah);
}

__global__ void __launch_bounds__(512) k_finish(const float* __restrict__ anchors,
                                                const float* __restrict__ gtb,
                                                const float* __restrict__ deltas,
                                                const float* __restrict__ rs,
                                                float* __restrict__ out) {
    const int n = blockIdx.x;
    const int tid = threadIdx.x;
    __shared__ float4 sg[MG];
    __shared__ unsigned cF[NBUCKC], cB[NBUCKC];   // raw counts
    __shared__ unsigned sF[NBUCKC], sB[NBUCKC];   // suffix sums
    __shared__ unsigned long long kF[CAPC], kB[CAPC];
    __shared__ unsigned long long scutF, scutB;
    __shared__ int sbF, sbB;
    __shared__ unsigned sneedF, sneedB, squota;
    __shared__ unsigned slist[TOTAL_K];
    __shared__ unsigned scnt;

    if (tid < MG) sg[tid] = ((const float4*)gtb)[n * MG + tid];
    if (tid < NBUCKC) {
        unsigned v = g_bcnt[(unsigned)(n * 2 + 1) * NBUCKC + tid];
        cF[tid] = v; sF[tid] = v;
    } else {
        unsigned v = g_bcnt[(unsigned)(n * 2 + 0) * NBUCKC + (tid - NBUCKC)];
        cB[tid - NBUCKC] = v; sB[tid - NBUCKC] = v;
    }
    if (tid == 0) { scutF = 0ull; scutB = 0ull; sbF = -1; sbB = -1; scnt = 0; }
    __syncthreads();

    // parallel suffix sums (Hillis-Steele), F on tid<256, B on tid>=256
    {
        unsigned* s = (tid < NBUCKC) ? sF : sB;
        int i = tid & (NBUCKC - 1);
#pragma unroll
        for (int off = 1; off < NBUCKC; off <<= 1) {
            unsigned v = s[i] + ((i + off < NBUCKC) ? s[i + off] : 0u);
            __syncthreads();
            s[i] = v;
            __syncthreads();
        }
    }
    if (tid == 0) {
        unsigned totF = sF[0];
        squota = TOTAL_K - (totF < MAXFG ? totF : MAXFG);
    }
    __syncthreads();
    const unsigned quota = squota;

    // boundary buckets (parallel: exactly one thread matches per class)
    if (tid < NBUCKC) {
        int b = tid;
        unsigned above = (b == NBUCKC - 1) ? 0u : sF[b + 1];
        if (sF[b] >= MAXFG && above < MAXFG) { sbF = b; sneedF = MAXFG - above; }
    } else {
        int b = tid - NBUCKC;
        unsigned above = (b == NBUCKC - 1) ? 0u : sB[b + 1];
        if (sB[b] >= quota && above < quota) { sbB = b; sneedB = quota - above; }
    }
    __syncthreads();

    // load boundary lists
    const unsigned LF = (sbF >= 0) ? (cF[sbF] < CAPC ? cF[sbF] : CAPC) : 0u;
    const unsigned LB = (sbB >= 0) ? (cB[sbB] < CAPC ? cB[sbB] : CAPC) : 0u;
    for (unsigned i = tid; i < LF; i += 512)
        kF[i] = g_blist[((size_t)((n * 2 + 1) * NBUCKC + sbF)) * CAPC + i];
    for (unsigned i = tid; i < LB; i += 512)
        kB[i] = g_blist[((size_t)((n * 2 + 0) * NBUCKC + sbB)) * CAPC + i];
    __syncthreads();

    // rank-select cutoff inside boundary bucket (keys distinct)
    for (unsigned i = tid; i < LF; i += 512) {
        unsigned long long k = kF[i];
        unsigned c = 0;
        for (unsigned j = 0; j < LF; j++) c += (kF[j] > k);
        if (c == sneedF - 1) scutF = k;
    }
    for (unsigned i = tid; i < LB; i += 512) {
        unsigned long long k = kB[i];
        unsigned c = 0;
        for (unsigned j = 0; j < LB; j++) c += (kB[j] > k);
        if (c == sneedB - 1) scutB = k;
    }
    __syncthreads();
    const unsigned long long cutF = scutF, cutB = scutB;

    // enumerate kept set directly from bucket lists
    if (tid < NBUCKC) {               // fg buckets
        int b = tid;
        if (sbF < 0 || b > sbF) {
            unsigned c = cF[b] < CAPC ? cF[b] : CAPC;
            size_t base = ((size_t)((n * 2 + 1) * NBUCKC + b)) * CAPC;
            for (unsigned j = 0; j < c; j++) {
                unsigned a = ~(unsigned)g_blist[base + j];
                unsigned slot = atomicAdd(&scnt, 1u);
                if (slot < TOTAL_K) slist[slot] = a | 0x80000000u;
            }
        }
    } else {                          // bg buckets
        int b = tid - NBUCKC;
        if (sbB < 0 || b > sbB) {
            unsigned c = cB[b] < CAPC ? cB[b] : CAPC;
            size_t base = ((size_t)((n * 2 + 0) * NBUCKC + b)) * CAPC;
            for (unsigned j = 0; j < c; j++) {
                unsigned a = ~(unsigned)g_blist[base + j];
                unsigned slot = atomicAdd(&scnt, 1u);
                if (slot < TOTAL_K) slist[slot] = a;
            }
        }
    }
    // boundary-bucket members above cutoff
    for (unsigned i = tid; i < LF; i += 512) {
        if (kF[i] >= cutF) {
            unsigned a = ~(unsigned)kF[i];
            unsigned slot = atomicAdd(&scnt, 1u);
            if (slot < TOTAL_K) slist[slot] = a | 0x80000000u;
        }
    }
    for (unsigned i = tid; i < LB; i += 512) {
        if (kB[i] >= cutB) {
            unsigned a = ~(unsigned)kB[i];
            unsigned slot = atomicAdd(&scnt, 1u);
            if (slot < TOTAL_K) slist[slot] = a;
        }
    }
    __syncthreads();
    unsigned cnt = scnt < TOTAL_K ? scnt : TOTAL_K;

    // rank-sort by anchor index ascending, then write
    if (tid < (int)cnt) {
        unsigned e = slist[tid];
        unsigned ai = e & 0x7FFFFFFFu;
        unsigned rank = 0;
        for (unsigned j = 0; j < cnt; j++)
            rank += ((slist[j] & 0x7FFFFFFFu) < ai);
        write_out(out, n, rank, (int)ai, (e & 0x80000000u) != 0, sg,
                  anchors, deltas + (size_t)n * AN * 4);
    }
    // pad tail with anchor 0 (matches reference scatter-zeros semantics)
    if ((unsigned)tid >= cnt && tid < TOTAL_K) {
        signed char lab0 = g_label[(size_t)n * AN + 0];   // a'=0 <-> a=0
        bool fg0 = false;
        if (lab0 == 1) fg0 = (keyf(rs[(size_t)n * AN + 0], 0) >= cutF);
        write_out(out, n, (unsigned)tid, 0, fg0, sg,
                  anchors, deltas + (size_t)n * AN * 4);
    }
}

// ----- launch ---------------------------------------------------------------
extern "C" void kernel_launch(void* const* d_in, const int* in_sizes, int n_in,
                              void* d_out, int out_size) {
    const float *anchors = nullptr, *gtb = nullptr, *deltas = nullptr, *rsc = nullptr;
    for (int i = 0; i < n_in; i++) {
        int s = in_sizes[i];
        if (s == AN * 4)           anchors = (const float*)d_in[i];
        else if (s == NI * MG * 4) gtb     = (const float*)d_in[i];
        else if (s == NI * AN * 4) deltas  = (const float*)d_in[i];
        else if (s == NI * AN)     rsc     = (const float*)d_in[i];
    }
    float* out = (float*)d_out;

    k_init<<<(NI * 2 * NBUCKC + 255) / 256, 256>>>();
    dim3 g1(NPOS / PCHUNK, NI);   // (16, 32)
    k_pass1<<<g1, PCHUNK>>>(anchors, gtb, deltas);
    k_pass2<<<g1, PCHUNK>>>(anchors, gtb, deltas, rsc);
    k_finish<<<NI, 512>>>(anchors, gtb, deltas, rsc, out);
}

// round 5
// speedup vs baseline: 7.7144x; 1.1456x over previous
#include <cuda_runtime.h>

// ---------------------------------------------------------------------------
// AnchorRefine R5:
//  - pass1: redux.sync warp extents, encoded-domain feasibility, bit-mask loop
//  - pass2: a_box upgrade + key append into 256 coarse r-buckets (no labels)
//  - finish: binary-search parallel enumeration of kept set, rank-sort,
//            outputs, and scratch self-reset (replaces init kernel)
// Output f32 buffer 49152: [0,8192) idx, [8192,16384) fg, [16384,49152) coeff.
// Scratch layout a' = type*4096 + pos; real anchor index a = pos*9 + type.
// Key = (r_bits<<32) | ~a  -> rank_desc order with stable tie-break.
// g_pgm encoding: ordered-uint encf(v); 0 is identity (all contributions > 0).
// ---------------------------------------------------------------------------

#define AN      36864
#define NPOS    4096
#define NTYPE   9
#define NI      32
#define MG      32
#define TOTAL_K 256
#define MAXFG   128
#define POS_T   0.7f
#define NEG_T   0.3f
#define IMGSZ   1024.0f
#define NBUCKC  256
#define CAPC    512
#define PCHUNK  256

// ----- device scratch (zero-initialized at load; finish self-resets) -------
__device__ __align__(16) float g_amax [NI * AN];                 // [n][a']
__device__ unsigned            g_pgm  [NI * MG];                 // 0 = identity
__device__ unsigned            g_bcnt [NI * 2 * NBUCKC];         // 0 = empty
__device__ unsigned long long  g_blist[(size_t)NI * 2 * NBUCKC * CAPC];

// ----- helpers -------------------------------------------------------------
__device__ __forceinline__ unsigned encf(float f) {
    unsigned b = __float_as_uint(f);
    return (b & 0x80000000u) ? ~b : (b | 0x80000000u);
}
__device__ __forceinline__ float decf(unsigned u) {
    unsigned b = (u & 0x80000000u) ? (u ^ 0x80000000u) : ~u;
    return __uint_as_float(b);
}
__device__ __forceinline__ unsigned fenc(float f) {   // monotone float->u32
    unsigned u = __float_as_uint(f);
    return u ^ (unsigned)(((int)u >> 31) | 0x80000000);
}
__device__ __forceinline__ int bucketc(float r) {
    int b = (int)(r * 256.0f);
    return b < 0 ? 0 : (b > 255 ? 255 : b);
}
__device__ __forceinline__ unsigned long long keyf(float r, int a) {
    return (((unsigned long long)__float_as_uint(r)) << 32)
         | (unsigned)(0xFFFFFFFFu - (unsigned)a);
}

// bbox_transform, exact reference op order, no FMA contraction.
__device__ __forceinline__ void predbox(float4 an, float4 d, float* b,
                                        float* areaA, bool* valid) {
    float w  = __fadd_rn(__fsub_rn(an.z, an.x), 1.0f);
    float h  = __fadd_rn(__fsub_rn(an.w, an.y), 1.0f);
    float cx = __fadd_rn(an.x, __fmul_rn(0.5f, w));
    float cy = __fadd_rn(an.y, __fmul_rn(0.5f, h));
    float pcx = __fadd_rn(__fmul_rn(d.x, w), cx);
    float pcy = __fadd_rn(__fmul_rn(d.y, h), cy);
    float pw  = __fmul_rn(expf(d.z), w);
    float ph  = __fmul_rn(expf(d.w), h);
    b[0] = __fsub_rn(pcx, __fmul_rn(0.5f, pw));
    b[1] = __fsub_rn(pcy, __fmul_rn(0.5f, ph));
    b[2] = __fadd_rn(pcx, __fmul_rn(0.5f, pw));
    b[3] = __fadd_rn(pcy, __fmul_rn(0.5f, ph));
    *areaA = __fmul_rn(__fadd_rn(__fsub_rn(b[2], b[0]), 1.0f),
                       __fadd_rn(__fsub_rn(b[3], b[1]), 1.0f));
    *valid = (b[0] >= 0.0f) && (b[1] >= 0.0f) && (b[2] < IMGSZ) && (b[3] < IMGSZ);
}

__device__ __forceinline__ float iou_div(float inter, float areaA, float ag) {
    return __fdiv_rn(inter, __fsub_rn(__fadd_rn(areaA, ag), inter));
}

// ----- K1: pred boxes, anchor_max, per-gt max ------------------------------
__global__ void __launch_bounds__(256) k_pass1(const float* __restrict__ anchors,
                                               const float* __restrict__ gtb,
                                               const float* __restrict__ deltas) {
    const int n = blockIdx.y;
    const int tid = threadIdx.x;
    const int lane = tid & 31;
    const int w = tid >> 5;
    // 2D warp tile: warp covers 8 cols x 4 rows of positions
    const int px = ((w & 7) << 3) + (lane & 7);             // 0..63
    const int py = (blockIdx.x << 2) + (lane >> 3);         // 0..63
    const int p  = (py << 6) + px;

    __shared__ float4 sg[MG];
    __shared__ float  sga[MG];
    __shared__ float  sred[8][MG];
    if (tid < MG) {
        float4 g = ((const float4*)gtb)[n * MG + tid];
        sg[tid] = g;
        sga[tid] = __fmul_rn(__fadd_rn(__fsub_rn(g.z, g.x), 1.0f),
                             __fadd_rn(__fsub_rn(g.w, g.y), 1.0f));
    }
    __syncthreads();
    const float4 gl = sg[lane];
    // encoded loose feasibility thresholds (conservative slack 2 px)
    const unsigned eGz = fenc(gl.z + 2.0f);   // need min b0 <= gz+2
    const unsigned eGx = fenc(gl.x - 2.0f);   // need max b2 >= gx-2
    const unsigned eGw = fenc(gl.w + 2.0f);   // need min b1 <= gw+2
    const unsigned eGy = fenc(gl.y - 2.0f);   // need max b3 >= gy-2

    float lmax[MG];
#pragma unroll
    for (int m = 0; m < MG; m++) lmax[m] = -1.0f;
    bool anyv = false;

    for (int type = 0; type < NTYPE; type++) {
        const int a  = p * NTYPE + type;
        const int ap = type * NPOS + p;
        float4 an = ((const float4*)anchors)[a];
        float4 d  = ((const float4*)deltas)[n * AN + a];
        float b[4], areaA; bool valid;
        predbox(an, d, b, &areaA, &valid);

        unsigned vball = __ballot_sync(0xFFFFFFFFu, valid);
        if (!vball) { g_amax[n * AN + ap] = -1.0f; continue; }
        anyv = true;

        // warp extents over valid lanes via redux on encoded floats
        unsigned e0 = valid ? fenc(b[0]) : 0xFFFFFFFFu;
        unsigned e1 = valid ? fenc(b[1]) : 0xFFFFFFFFu;
        unsigned e2 = valid ? fenc(b[2]) : 0u;
        unsigned e3 = valid ? fenc(b[3]) : 0u;
        unsigned b0m = __reduce_min_sync(0xFFFFFFFFu, e0);
        unsigned b1m = __reduce_min_sync(0xFFFFFFFFu, e1);
        unsigned b2M = __reduce_max_sync(0xFFFFFFFFu, e2);
        unsigned b3M = __reduce_max_sync(0xFFFFFFFFu, e3);
        bool poss = (b0m <= eGz) && (b2M >= eGx) && (b1m <= eGw) && (b3M >= eGy);
        unsigned mask = __ballot_sync(0xFFFFFFFFu, poss);   // warp-uniform

        float amax = -1.0f;
        if (valid) {
            amax = 0.0f;
            unsigned mm = mask;
            while (mm) {
                int m = __ffs(mm) - 1;
                mm &= mm - 1;
                float4 g = sg[m];
                float iw = __fadd_rn(__fsub_rn(fminf(b[2], g.z), fmaxf(b[0], g.x)), 1.0f);
                float ih = __fadd_rn(__fsub_rn(fminf(b[3], g.w), fmaxf(b[1], g.y)), 1.0f);
                if (iw > 0.0f && ih > 0.0f) {
                    float inter = __fmul_rn(iw, ih);
                    float ov = iou_div(inter, areaA, sga[m]);
                    amax = fmaxf(amax, ov);
                    lmax[m] = fmaxf(lmax[m], ov);
                }
            }
        }
        g_amax[n * AN + ap] = amax;
    }

#pragma unroll
    for (int m = 0; m < MG; m++) {
        float v = lmax[m];
        for (int off = 16; off; off >>= 1)
            v = fmaxf(v, __shfl_xor_sync(0xFFFFFFFFu, v, off));
        if (lane == 0) sred[w][m] = v;
    }
    int anyv_all = __syncthreads_or(anyv ? 1 : 0);
    if (tid < MG) {
        float v = sred[0][tid];
#pragma unroll
        for (int ww = 1; ww < 8; ww++) v = fmaxf(v, sred[ww][tid]);
        if (anyv_all) v = fmaxf(v, 0.0f);   // valid anchors contribute ov >= 0
        atomicMax(&g_pgm[n * MG + tid], encf(v));
    }
}

// ----- K2: a_box upgrade + final labels + bucket key append ----------------
__global__ void __launch_bounds__(256) k_pass2(const float* __restrict__ anchors,
                                               const float* __restrict__ gtb,
                                               const float* __restrict__ deltas,
                                               const float* __restrict__ rs) {
    const int n = blockIdx.y;
    const int tid = threadIdx.x;
    const int p = blockIdx.x * PCHUNK + tid;
    __shared__ float4 sg[MG];
    __shared__ float  sga[MG];
    __shared__ float  spgm[MG];
    __shared__ float  sminp;
    if (tid < MG) {
        float4 g = ((const float4*)gtb)[n * MG + tid];
        sg[tid] = g;
        sga[tid] = __fmul_rn(__fadd_rn(__fsub_rn(g.z, g.x), 1.0f),
                             __fadd_rn(__fsub_rn(g.w, g.y), 1.0f));
        spgm[tid] = decf(g_pgm[n * MG + tid]);
    }
    __syncthreads();
    if (tid == 0) {
        float mn = spgm[0];
        for (int m = 1; m < MG; m++) mn = fminf(mn, spgm[m]);
        sminp = mn;
    }
    __syncthreads();

    for (int type = 0; type < NTYPE; type++) {
        const int a  = p * NTYPE + type;
        const int ap = type * NPOS + p;
        float amax = g_amax[n * AN + ap];
        signed char lab = (amax >= POS_T) ? 1
                        : ((amax >= 0.0f && amax < NEG_T) ? 0 : -1);
        if (lab != 1 && amax >= 0.0f && amax >= sminp) {  // a_box necessary cond
            float4 an = ((const float4*)anchors)[a];
            float4 d  = ((const float4*)deltas)[n * AN + a];
            float b[4], areaA; bool valid;
            predbox(an, d, b, &areaA, &valid);
            bool abox = false;
#pragma unroll 4
            for (int m = 0; m < MG; m++) {
                float pm = spgm[m];
                if (pm <= amax) {
                    float4 g = sg[m];
                    float iw = __fadd_rn(__fsub_rn(fminf(b[2], g.z), fmaxf(b[0], g.x)), 1.0f);
                    float ih = __fadd_rn(__fsub_rn(fminf(b[3], g.w), fmaxf(b[1], g.y)), 1.0f);
                    if (iw > 0.0f && ih > 0.0f) {
                        float inter = __fmul_rn(iw, ih);
                        float ov = iou_div(inter, areaA, sga[m]);
                        abox |= (ov == pm);
                    } else {
                        abox |= (pm == 0.0f);
                    }
                }
            }
            if (abox) lab = 1;
        }
        if (lab >= 0) {
            float r = rs[n * AN + a];
            int bk = bucketc(r);
            unsigned base = (unsigned)(n * 2 + lab) * NBUCKC + bk;
            unsigned q = atomicAdd(&g_bcnt[base], 1u);
            if (q < CAPC) g_blist[(size_t)base * CAPC + q] = keyf(r, a);
        }
    }
}

// ----- K3: cutoffs + parallel enumeration + outputs + scratch reset --------
__device__ __forceinline__ void write_out(float* out, int n, unsigned p, int a,
                                          bool fg, const float4* sg,
                                          const float* anchors,
                                          const float* deltasImg) {
    float4 A4 = ((const float4*)anchors)[a];
    float4 d  = ((const float4*)deltasImg)[a];
    float b[4], areaA; bool valid;
    predbox(A4, d, b, &areaA, &valid);
    int gid = 0;
    if (valid) {
        float best = -1.0f;
#pragma unroll 4
        for (int m = 0; m < MG; m++) {
            float4 g = sg[m];
            float ag = __fmul_rn(__fadd_rn(__fsub_rn(g.z, g.x), 1.0f),
                                 __fadd_rn(__fsub_rn(g.w, g.y), 1.0f));
            float iw = fmaxf(__fadd_rn(__fsub_rn(fminf(b[2], g.z), fmaxf(b[0], g.x)), 1.0f), 0.0f);
            float ih = fmaxf(__fadd_rn(__fsub_rn(fminf(b[3], g.w), fmaxf(b[1], g.y)), 1.0f), 0.0f);
            float inter = __fmul_rn(iw, ih);
            float ov = iou_div(inter, areaA, ag);
            if (ov > best) { best = ov; gid = m; }
        }
    }
    float4 G = sg[gid];
    float aw = A4.z - A4.x + 1.0f, ah = A4.w - A4.y + 1.0f;
    float acx = A4.x + 0.5f * aw, acy = A4.y + 0.5f * ah;
    float gw = G.z - G.x + 1.0f, gh = G.w - G.y + 1.0f;
    float gcx = G.x + 0.5f * gw, gcy = G.y + 0.5f * gh;
    out[n * TOTAL_K + p] = (float)a;
    out[NI * TOTAL_K + n * TOTAL_K + p] = fg ? 1.0f : 0.0f;
    float* c = &out[2 * NI * TOTAL_K + (unsigned)(n * TOTAL_K + p) * 4u];
    c[0] = (gcx - acx) / aw;
    c[1] = (gcy - acy) / ah;
    c[2] = logf(gw / aw);
    c[3] = logf(gh / ah);
}

__global__ void __launch_bounds__(512) k_finish(const float* __restrict__ anchors,
                                                const float* __restrict__ gtb,
                                                const float* __restrict__ deltas,
                                                const float* __restrict__ rs,
                                                float* __restrict__ out) {
    const int n = blockIdx.x;
    const int tid = threadIdx.x;
    __shared__ float4 sg[MG];
    __shared__ float  spgm[MG];
    __shared__ unsigned cF[NBUCKC], cB[NBUCKC];   // raw counts
    __shared__ unsigned sF[NBUCKC], sB[NBUCKC];   // suffix sums
    __shared__ unsigned long long kF[CAPC], kB[CAPC];
    __shared__ unsigned long long scutF, scutB;
    __shared__ int sbF, sbB;
    __shared__ unsigned sneedF, sneedB, squota;
    __shared__ unsigned slist[TOTAL_K];
    __shared__ unsigned scnt;
    __shared__ unsigned sfg0;

    if (tid < MG) {
        sg[tid] = ((const float4*)gtb)[n * MG + tid];
        spgm[tid] = decf(g_pgm[n * MG + tid]);
        g_pgm[n * MG + tid] = 0u;                          // reset for next run
    }
    if (tid < NBUCKC) {
        unsigned idx = (unsigned)(n * 2 + 1) * NBUCKC + tid;
        unsigned v = g_bcnt[idx];
        g_bcnt[idx] = 0u;                                  // reset for next run
        cF[tid] = v; sF[tid] = v;
    } else {
        unsigned idx = (unsigned)(n * 2 + 0) * NBUCKC + (tid - NBUCKC);
        unsigned v = g_bcnt[idx];
        g_bcnt[idx] = 0u;                                  // reset for next run
        cB[tid - NBUCKC] = v; sB[tid - NBUCKC] = v;
    }
    if (tid == 0) { scutF = 0ull; scutB = 0ull; sbF = -1; sbB = -1;
                    scnt = 0; sfg0 = 0; }
    __syncthreads();

    // parallel suffix sums (Hillis-Steele), F on tid<256, B on tid>=256
    {
        unsigned* s = (tid < NBUCKC) ? sF : sB;
        int i = tid & (NBUCKC - 1);
#pragma unroll
        for (int off = 1; off < NBUCKC; off <<= 1) {
            unsigned v = s[i] + ((i + off < NBUCKC) ? s[i + off] : 0u);
            __syncthreads();
            s[i] = v;
            __syncthreads();
        }
    }
    if (tid == 0) {
        unsigned totF = sF[0];
        squota = TOTAL_K - (totF < MAXFG ? totF : MAXFG);
    }
    __syncthreads();
    const unsigned quota = squota;

    // boundary buckets (exactly one thread matches per class)
    if (tid < NBUCKC) {
        int b = tid;
        unsigned above = (b == NBUCKC - 1) ? 0u : sF[b + 1];
        if (sF[b] >= MAXFG && above < MAXFG) { sbF = b; sneedF = MAXFG - above; }
    } else {
        int b = tid - NBUCKC;
        unsigned above = (b == NBUCKC - 1) ? 0u : sB[b + 1];
        if (sB[b] >= quota && above < quota) { sbB = b; sneedB = quota - above; }
    }
    __syncthreads();

    // load boundary lists (parallel, coalesced)
    const unsigned LF = (sbF >= 0) ? (cF[sbF] < CAPC ? cF[sbF] : CAPC) : 0u;
    const unsigned LB = (sbB >= 0) ? (cB[sbB] < CAPC ? cB[sbB] : CAPC) : 0u;
    for (unsigned i = tid; i < LF; i += 512)
        kF[i] = g_blist[((size_t)((n * 2 + 1) * NBUCKC + sbF)) * CAPC + i];
    for (unsigned i = tid; i < LB; i += 512)
        kB[i] = g_blist[((size_t)((n * 2 + 0) * NBUCKC + sbB)) * CAPC + i];
    __syncthreads();

    // rank-select cutoff inside boundary bucket (keys distinct)
    for (unsigned i = tid; i < LF; i += 512) {
        unsigned long long k = kF[i];
        unsigned c = 0;
        for (unsigned j = 0; j < LF; j++) c += (kF[j] > k);
        if (c == sneedF - 1) scutF = k;
    }
    for (unsigned i = tid; i < LB; i += 512) {
        unsigned long long k = kB[i];
        unsigned c = 0;
        for (unsigned j = 0; j < LB; j++) c += (kB[j] > k);
        if (c == sneedB - 1) scutB = k;
    }
    __syncthreads();
    const unsigned long long cutF = scutF, cutB = scutB;

    // --- parallel enumeration of entries strictly above the boundary bucket.
    // thread t binary-searches the suffix-sum array for its (bucket, j).
    const unsigned totAF = (sbF >= 0) ? ((sbF == NBUCKC - 1) ? 0u : sF[sbF + 1])
                                      : sF[0];
    const unsigned totAB = (sbB >= 0) ? ((sbB == NBUCKC - 1) ? 0u : sB[sbB + 1])
                                      : sB[0];
    for (unsigned t = tid; t < totAF; t += 512) {
        int lo = 0, hi = NBUCKC - 1;                 // largest b with sF[b] > t
        while (lo < hi) { int mid = (lo + hi + 1) >> 1;
                          if (sF[mid] > t) lo = mid; else hi = mid - 1; }
        unsigned prev = (lo == NBUCKC - 1) ? 0u : sF[lo + 1];
        unsigned j = t - prev;
        if (j < CAPC) {
            unsigned long long k =
                g_blist[((size_t)((n * 2 + 1) * NBUCKC + lo)) * CAPC + j];
            unsigned slot = atomicAdd(&scnt, 1u);
            if (slot < TOTAL_K) slist[slot] = (~(unsigned)k) | 0x80000000u;
        }
    }
    for (unsigned t = tid; t < totAB; t += 512) {
        int lo = 0, hi = NBUCKC - 1;
        while (lo < hi) { int mid = (lo + hi + 1) >> 1;
                          if (sB[mid] > t) lo = mid; else hi = mid - 1; }
        unsigned prev = (lo == NBUCKC - 1) ? 0u : sB[lo + 1];
        unsigned j = t - prev;
        if (j < CAPC) {
            unsigned long long k =
                g_blist[((size_t)((n * 2 + 0) * NBUCKC + lo)) * CAPC + j];
            unsigned slot = atomicAdd(&scnt, 1u);
            if (slot < TOTAL_K) slist[slot] = (~(unsigned)k);
        }
    }
    // boundary-bucket survivors (exactly sneed per class)
    for (unsigned i = tid; i < LF; i += 512) {
        if (kF[i] >= cutF) {
            unsigned slot = atomicAdd(&scnt, 1u);
            if (slot < TOTAL_K) slist[slot] = (~(unsigned)kF[i]) | 0x80000000u;
        }
    }
    for (unsigned i = tid; i < LB; i += 512) {
        if (kB[i] >= cutB) {
            unsigned slot = atomicAdd(&scnt, 1u);
            if (slot < TOTAL_K) slist[slot] = (~(unsigned)kB[i]);
        }
    }
    __syncthreads();
    unsigned cnt = scnt < TOTAL_K ? scnt : TOTAL_K;

    // pad-tail fg flag for anchor 0 (rare path: bg pool smaller than quota)
    if (tid == 0 && cnt < TOTAL_K) {
        float amax0 = g_amax[(size_t)n * AN + 0];    // a'=0 <-> a=0
        int lab0 = (amax0 >= POS_T) ? 1 : -1;
        if (lab0 != 1 && amax0 >= 0.0f) {
            float4 A4 = ((const float4*)anchors)[0];
            float4 d  = ((const float4*)(deltas + (size_t)n * AN * 4))[0];
            float b[4], areaA; bool valid;
            predbox(A4, d, b, &areaA, &valid);
            for (int m = 0; m < MG; m++) {
                float pm = spgm[m];
                if (pm <= amax0) {
                    float4 g = sg[m];
                    float ag = __fmul_rn(__fadd_rn(__fsub_rn(g.z, g.x), 1.0f),
                                         __fadd_rn(__fsub_rn(g.w, g.y), 1.0f));
                    float iw = __fadd_rn(__fsub_rn(fminf(b[2], g.z), fmaxf(b[0], g.x)), 1.0f);
                    float ih = __fadd_rn(__fsub_rn(fminf(b[3], g.w), fmaxf(b[1], g.y)), 1.0f);
                    if (iw > 0.0f && ih > 0.0f) {
                        float inter = __fmul_rn(iw, ih);
                        if (iou_div(inter, areaA, ag) == pm) lab0 = 1;
                    } else if (pm == 0.0f) lab0 = 1;
                }
            }
        }
        if (lab0 == 1 && keyf(rs[(size_t)n * AN + 0], 0) >= cutF) sfg0 = 1;
    }
    __syncthreads();

    // rank-sort by anchor index ascending, then write
    if (tid < (int)cnt) {
        unsigned e = slist[tid];
        unsigned ai = e & 0x7FFFFFFFu;
        unsigned rank = 0;
        for (unsigned j = 0; j < cnt; j++)
            rank += ((slist[j] & 0x7FFFFFFFu) < ai);
        write_out(out, n, rank, (int)ai, (e & 0x80000000u) != 0, sg,
                  anchors, deltas + (size_t)n * AN * 4);
    }
    if ((unsigned)tid >= cnt && tid < TOTAL_K) {
        write_out(out, n, (unsigned)tid, 0, sfg0 != 0, sg,
                  anchors, deltas + (size_t)n * AN * 4);
    }
}

// ----- launch ---------------------------------------------------------------
extern "C" void kernel_launch(void* const* d_in, const int* in_sizes, int n_in,
                              void* d_out, int out_size) {
    const float *anchors = nullptr, *gtb = nullptr, *deltas = nullptr, *rsc = nullptr;
    for (int i = 0; i < n_in; i++) {
        int s = in_sizes[i];
        if (s == AN * 4)           anchors = (const float*)d_in[i];
        else if (s == NI * MG * 4) gtb     = (const float*)d_in[i];
        else if (s == NI * AN * 4) deltas  = (const float*)d_in[i];
        else if (s == NI * AN)     rsc     = (const float*)d_in[i];
    }
    float* out = (float*)d_out;

    dim3 g1(NPOS / PCHUNK, NI);   // (16, 32)
    k_pass1<<<g1, PCHUNK>>>(anchors, gtb, deltas);
    k_pass2<<<g1, PCHUNK>>>(anchors, gtb, deltas, rsc);
    k_finish<<<NI, 512>>>(anchors, gtb, deltas, rsc, out);
}

// round 7
// speedup vs baseline: 13.9612x; 1.8098x over previous
#include <cuda_runtime.h>

// ---------------------------------------------------------------------------
// AnchorRefine R6: type-split grids (16,32,9) for full occupancy.
//  - pass1: 1 anchor/thread, warp feasibility redux, sparse shared per-gt max
//  - pass2: 1 anchor/thread, a_box upgrade + key append into 256 r-buckets
//  - finish: per-image cutoffs, parallel kept-set enumeration, outputs,
//            scratch self-reset (device globals zero-init; finish re-zeroes)
// Output f32 buffer 49152: [0,8192) idx, [8192,16384) fg, [16384,49152) coeff.
// Scratch layout a' = type*4096 + pos; real anchor index a = pos*9 + type.
// Key = (r_bits<<32) | ~a  -> rank_desc order with stable tie-break.
// g_pgm: raw bits of nonneg float (uint order == float order); 0 = identity.
// ---------------------------------------------------------------------------

#define AN      36864
#define NPOS    4096
#define NTYPE   9
#define NI      32
#define MG      32
#define TOTAL_K 256
#define MAXFG   128
#define POS_T   0.7f
#define NEG_T   0.3f
#define IMGSZ   1024.0f
#define NBUCKC  256
#define CAPC    512
#define PCHUNK  256

// ----- device scratch (zero-initialized at load; finish self-resets) -------
__device__ __align__(16) float g_amax [NI * AN];                 // [n][a']
__device__ unsigned            g_pgm  [NI * MG];                 // 0 = identity
__device__ unsigned            g_bcnt [NI * 2 * NBUCKC];         // 0 = empty
__device__ unsigned long long  g_blist[(size_t)NI * 2 * NBUCKC * CAPC];

// ----- helpers -------------------------------------------------------------
__device__ __forceinline__ int bucketc(float r) {
    int b = (int)(r * 256.0f);
    return b < 0 ? 0 : (b > 255 ? 255 : b);
}
__device__ __forceinline__ unsigned long long keyf(float r, int a) {
    return (((unsigned long long)__float_as_uint(r)) << 32)
         | (unsigned)(0xFFFFFFFFu - (unsigned)a);
}

// bbox_transform, exact reference op order, no FMA contraction.
__device__ __forceinline__ void predbox(float4 an, float4 d, float* b,
                                        float* areaA, bool* valid) {
    float w  = __fadd_rn(__fsub_rn(an.z, an.x), 1.0f);
    float h  = __fadd_rn(__fsub_rn(an.w, an.y), 1.0f);
    float cx = __fadd_rn(an.x, __fmul_rn(0.5f, w));
    float cy = __fadd_rn(an.y, __fmul_rn(0.5f, h));
    float pcx = __fadd_rn(__fmul_rn(d.x, w), cx);
    float pcy = __fadd_rn(__fmul_rn(d.y, h), cy);
    float pw  = __fmul_rn(expf(d.z), w);
    float ph  = __fmul_rn(expf(d.w), h);
    b[0] = __fsub_rn(pcx, __fmul_rn(0.5f, pw));
    b[1] = __fsub_rn(pcy, __fmul_rn(0.5f, ph));
    b[2] = __fadd_rn(pcx, __fmul_rn(0.5f, pw));
    b[3] = __fadd_rn(pcy, __fmul_rn(0.5f, ph));
    *areaA = __fmul_rn(__fadd_rn(__fsub_rn(b[2], b[0]), 1.0f),
                       __fadd_rn(__fsub_rn(b[3], b[1]), 1.0f));
    *valid = (b[0] >= 0.0f) && (b[1] >= 0.0f) && (b[2] < IMGSZ) && (b[3] < IMGSZ);
}

__device__ __forceinline__ float iou_div(float inter, float areaA, float ag) {
    return __fdiv_rn(inter, __fsub_rn(__fadd_rn(areaA, ag), inter));
}

// ----- K1: pred boxes, anchor_max, per-gt max (type-split) -----------------
__global__ void __launch_bounds__(256) k_pass1(const float* __restrict__ anchors,
                                               const float* __restrict__ gtb,
                                               const float* __restrict__ deltas) {
    const int n    = blockIdx.y;
    const int type = blockIdx.z;
    const int tid  = threadIdx.x;
    const int lane = tid & 31;
    const int w    = tid >> 5;
    // 2D warp tile: warp covers 8 cols x 4 rows of positions
    const int px = ((w & 7) << 3) + (lane & 7);             // 0..63
    const int py = (blockIdx.x << 2) + (lane >> 3);         // 0..63
    const int p  = (py << 6) + px;

    __shared__ float4   sg[MG];
    __shared__ float    sga[MG];
    __shared__ unsigned slmax[MG];
    if (tid < MG) {
        float4 g = ((const float4*)gtb)[n * MG + tid];
        sg[tid] = g;
        sga[tid] = __fmul_rn(__fadd_rn(__fsub_rn(g.z, g.x), 1.0f),
                             __fadd_rn(__fsub_rn(g.w, g.y), 1.0f));
        slmax[tid] = 0u;
    }
    __syncthreads();
    const float4 gl = sg[lane];
    // loose feasibility thresholds (conservative slack 2 px, clamped >= 0;
    // valid boxes have all coords >= 0, so raw float bits order correctly)
    const unsigned eGz = __float_as_uint(gl.z + 2.0f);           // min b0 <= gz+2
    const unsigned eGx = __float_as_uint(fmaxf(gl.x - 2.0f, 0.0f)); // max b2 >= gx-2
    const unsigned eGw = __float_as_uint(gl.w + 2.0f);           // min b1 <= gw+2
    const unsigned eGy = __float_as_uint(fmaxf(gl.y - 2.0f, 0.0f)); // max b3 >= gy-2

    const int a  = p * NTYPE + type;
    const int ap = type * NPOS + p;
    float4 an = ((const float4*)anchors)[a];
    float4 d  = ((const float4*)deltas)[n * AN + a];
    float b[4], areaA; bool valid;
    predbox(an, d, b, &areaA, &valid);

    float amax = valid ? 0.0f : -1.0f;
    unsigned vball = __ballot_sync(0xFFFFFFFFu, valid);
    if (vball) {
        // warp extents over valid lanes (raw bits, sentinels for invalid)
        unsigned e0 = valid ? __float_as_uint(b[0]) : 0xFFFFFFFFu;
        unsigned e1 = valid ? __float_as_uint(b[1]) : 0xFFFFFFFFu;
        unsigned e2 = valid ? __float_as_uint(b[2]) : 0u;
        unsigned e3 = valid ? __float_as_uint(b[3]) : 0u;
        unsigned b0m = __reduce_min_sync(0xFFFFFFFFu, e0);
        unsigned b1m = __reduce_min_sync(0xFFFFFFFFu, e1);
        unsigned b2M = __reduce_max_sync(0xFFFFFFFFu, e2);
        unsigned b3M = __reduce_max_sync(0xFFFFFFFFu, e3);
        bool poss = (b0m <= eGz) && (b2M >= eGx) && (b1m <= eGw) && (b3M >= eGy);
        unsigned mm = __ballot_sync(0xFFFFFFFFu, poss);   // warp-uniform mask

        while (mm) {
            int m = __ffs(mm) - 1;
            mm &= mm - 1;
            float4 g = sg[m];
            float iw = __fadd_rn(__fsub_rn(fminf(b[2], g.z), fmaxf(b[0], g.x)), 1.0f);
            float ih = __fadd_rn(__fsub_rn(fminf(b[3], g.w), fmaxf(b[1], g.y)), 1.0f);
            unsigned ovu = 0u;
            if (valid && iw > 0.0f && ih > 0.0f) {
                float inter = __fmul_rn(iw, ih);
                float ov = iou_div(inter, areaA, sga[m]);   // > 0
                amax = fmaxf(amax, ov);
                ovu = __float_as_uint(ov);
            }
            unsigned wmax = __reduce_max_sync(0xFFFFFFFFu, ovu);
            if (lane == 0 && wmax) atomicMax(&slmax[m], wmax);
        }
    }
    g_amax[n * AN + ap] = amax;

    __syncthreads();
    if (tid < MG && slmax[tid]) atomicMax(&g_pgm[n * MG + tid], slmax[tid]);
}

// ----- K2: a_box upgrade + labels + bucket key append (type-split) ---------
__global__ void __launch_bounds__(256) k_pass2(const float* __restrict__ anchors,
                                               const float* __restrict__ gtb,
                                               const float* __restrict__ deltas,
                                               const float* __restrict__ rs) {
    const int n    = blockIdx.y;
    const int type = blockIdx.z;
    const int tid  = threadIdx.x;
    const int p    = blockIdx.x * PCHUNK + tid;
    __shared__ float4 sg[MG];
    __shared__ float  sga[MG];
    __shared__ float  spgm[MG];
    __shared__ float  sminp;
    if (tid < MG) {
        float4 g = ((const float4*)gtb)[n * MG + tid];
        sg[tid] = g;
        sga[tid] = __fmul_rn(__fadd_rn(__fsub_rn(g.z, g.x), 1.0f),
                             __fadd_rn(__fsub_rn(g.w, g.y), 1.0f));
        spgm[tid] = __uint_as_float(g_pgm[n * MG + tid]);
    }
    __syncthreads();
    if (tid == 0) {
        float mn = spgm[0];
        for (int m = 1; m < MG; m++) mn = fminf(mn, spgm[m]);
        sminp = mn;
    }
    __syncthreads();

    const int a  = p * NTYPE + type;
    const int ap = type * NPOS + p;
    float amax = g_amax[n * AN + ap];
    int lab = (amax >= POS_T) ? 1 : ((amax >= 0.0f && amax < NEG_T) ? 0 : -1);
    if (lab != 1 && amax >= 0.0f && amax >= sminp) {      // a_box necessary cond
        float4 an = ((const float4*)anchors)[a];
        float4 d  = ((const float4*)deltas)[n * AN + a];
        float b[4], areaA; bool valid;
        predbox(an, d, b, &areaA, &valid);
        bool abox = false;
#pragma unroll 4
        for (int m = 0; m < MG; m++) {
            float pm = spgm[m];
            if (pm <= amax) {
                float4 g = sg[m];
                float iw = __fadd_rn(__fsub_rn(fminf(b[2], g.z), fmaxf(b[0], g.x)), 1.0f);
                float ih = __fadd_rn(__fsub_rn(fminf(b[3], g.w), fmaxf(b[1], g.y)), 1.0f);
                if (iw > 0.0f && ih > 0.0f) {
                    float inter = __fmul_rn(iw, ih);
                    float ov = iou_div(inter, areaA, sga[m]);
                    abox |= (ov == pm);
                } else {
                    abox |= (pm == 0.0f);
                }
            }
        }
        if (abox) lab = 1;
    }
    if (lab >= 0) {
        float r = rs[n * AN + a];
        int bk = bucketc(r);
        unsigned base = (unsigned)(n * 2 + lab) * NBUCKC + bk;
        unsigned q = atomicAdd(&g_bcnt[base], 1u);
        if (q < CAPC) g_blist[(size_t)base * CAPC + q] = keyf(r, a);
    }
}

// ----- K3: cutoffs + parallel enumeration + outputs + scratch reset --------
__device__ __forceinline__ void write_out(float* out, int n, unsigned p, int a,
                                          bool fg, const float4* sg,
                                          const float* anchors,
                                          const float* deltasImg) {
    float4 A4 = ((const float4*)anchors)[a];
    float4 d  = ((const float4*)deltasImg)[a];
    float b[4], areaA; bool valid;
    predbox(A4, d, b, &areaA, &valid);
    int gid = 0;
    if (valid) {
        float best = -1.0f;
#pragma unroll 4
        for (int m = 0; m < MG; m++) {
            float4 g = sg[m];
            float ag = __fmul_rn(__fadd_rn(__fsub_rn(g.z, g.x), 1.0f),
                                 __fadd_rn(__fsub_rn(g.w, g.y), 1.0f));
            float iw = fmaxf(__fadd_rn(__fsub_rn(fminf(b[2], g.z), fmaxf(b[0], g.x)), 1.0f), 0.0f);
            float ih = fmaxf(__fadd_rn(__fsub_rn(fminf(b[3], g.w), fmaxf(b[1], g.y)), 1.0f), 0.0f);
            float inter = __fmul_rn(iw, ih);
            float ov = iou_div(inter, areaA, ag);
            if (ov > best) { best = ov; gid = m; }
        }
    }
    float4 G = sg[gid];
    float aw = A4.z - A4.x + 1.0f, ah = A4.w - A4.y + 1.0f;
    float acx = A4.x + 0.5f * aw, acy = A4.y + 0.5f * ah;
    float gw = G.z - G.x + 1.0f, gh = G.w - G.y + 1.0f;
    float gcx = G.x + 0.5f * gw, gcy = G.y + 0.5f * gh;
    out[n * TOTAL_K + p] = (float)a;
    out[NI * TOTAL_K + n * TOTAL_K + p] = fg ? 1.0f : 0.0f;
    float* c = &out[2 * NI * TOTAL_K + (unsigned)(n * TOTAL_K + p) * 4u];
    c[0] = (gcx - acx) / aw;
    c[1] = (gcy - acy) / ah;
    c[2] = logf(gw / aw);
    c[3] = logf(gh / ah);
}

__global__ void __launch_bounds__(512) k_finish(const float* __restrict__ anchors,
                                                const float* __restrict__ gtb,
                                                const float* __restrict__ deltas,
                                                const float* __restrict__ rs,
                                                float* __restrict__ out) {
    const int n = blockIdx.x;
    const int tid = threadIdx.x;
    __shared__ float4 sg[MG];
    __shared__ float  spgm[MG];
    __shared__ unsigned cF[NBUCKC], cB[NBUCKC];   // raw counts
    __shared__ unsigned sF[NBUCKC], sB[NBUCKC];   // suffix sums
    __shared__ unsigned long long kF[CAPC], kB[CAPC];
    __shared__ unsigned long long scutF, scutB;
    __shared__ int sbF, sbB;
    __shared__ unsigned sneedF, sneedB, squota;
    __shared__ unsigned slist[TOTAL_K];
    __shared__ unsigned scnt;
    __shared__ unsigned sfg0;

    if (tid < MG) {
        sg[tid] = ((const float4*)gtb)[n * MG + tid];
        spgm[tid] = __uint_as_float(g_pgm[n * MG + tid]);
        g_pgm[n * MG + tid] = 0u;                          // reset for next run
    }
    if (tid < NBUCKC) {
        unsigned idx = (unsigned)(n * 2 + 1) * NBUCKC + tid;
        unsigned v = g_bcnt[idx];
        g_bcnt[idx] = 0u;                                  // reset for next run
        cF[tid] = v; sF[tid] = v;
    } else {
        unsigned idx = (unsigned)(n * 2 + 0) * NBUCKC + (tid - NBUCKC);
        unsigned v = g_bcnt[idx];
        g_bcnt[idx] = 0u;                                  // reset for next run
        cB[tid - NBUCKC] = v; sB[tid - NBUCKC] = v;
    }
    if (tid == 0) { scutF = 0ull; scutB = 0ull; sbF = -1; sbB = -1;
                    scnt = 0; sfg0 = 0; }
    __syncthreads();

    // parallel suffix sums (Hillis-Steele), F on tid<256, B on tid>=256
    {
        unsigned* s = (tid < NBUCKC) ? sF : sB;
        int i = tid & (NBUCKC - 1);
#pragma unroll
        for (int off = 1; off < NBUCKC; off <<= 1) {
            unsigned v = s[i] + ((i + off < NBUCKC) ? s[i + off] : 0u);
            __syncthreads();
            s[i] = v;
            __syncthreads();
        }
    }
    if (tid == 0) {
        unsigned totF = sF[0];
        squota = TOTAL_K - (totF < MAXFG ? totF : MAXFG);
    }
    __syncthreads();
    const unsigned quota = squota;

    // boundary buckets (exactly one thread matches per class)
    if (tid < NBUCKC) {
        int b = tid;
        unsigned above = (b == NBUCKC - 1) ? 0u : sF[b + 1];
        if (sF[b] >= MAXFG && above < MAXFG) { sbF = b; sneedF = MAXFG - above; }
    } else {
        int b = tid - NBUCKC;
        unsigned above = (b == NBUCKC - 1) ? 0u : sB[b + 1];
        if (sB[b] >= quota && above < quota) { sbB = b; sneedB = quota - above; }
    }
    __syncthreads();

    // load boundary lists (parallel, coalesced)
    const unsigned LF = (sbF >= 0) ? (cF[sbF] < CAPC ? cF[sbF] : CAPC) : 0u;
    const unsigned LB = (sbB >= 0) ? (cB[sbB] < CAPC ? cB[sbB] : CAPC) : 0u;
    for (unsigned i = tid; i < LF; i += 512)
        kF[i] = g_blist[((size_t)((n * 2 + 1) * NBUCKC + sbF)) * CAPC + i];
    for (unsigned i = tid; i < LB; i += 512)
        kB[i] = g_blist[((size_t)((n * 2 + 0) * NBUCKC + sbB)) * CAPC + i];
    __syncthreads();

    // rank-select cutoff inside boundary bucket (keys distinct)
    for (unsigned i = tid; i < LF; i += 512) {
        unsigned long long k = kF[i];
        unsigned c = 0;
        for (unsigned j = 0; j < LF; j++) c += (kF[j] > k);
        if (c == sneedF - 1) scutF = k;
    }
    for (unsigned i = tid; i < LB; i += 512) {
        unsigned long long k = kB[i];
        unsigned c = 0;
        for (unsigned j = 0; j < LB; j++) c += (kB[j] > k);
        if (c == sneedB - 1) scutB = k;
    }
    __syncthreads();
    const unsigned long long cutF = scutF, cutB = scutB;

    // parallel enumeration of entries strictly above the boundary bucket:
    // thread t binary-searches the suffix-sum array for its (bucket, j).
    const unsigned totAF = (sbF >= 0) ? ((sbF == NBUCKC - 1) ? 0u : sF[sbF + 1])
                                      : sF[0];
    const unsigned totAB = (sbB >= 0) ? ((sbB == NBUCKC - 1) ? 0u : sB[sbB + 1])
                                      : sB[0];
    for (unsigned t = tid; t < totAF; t += 512) {
        int lo = 0, hi = NBUCKC - 1;                 // largest b with sF[b] > t
        while (lo < hi) { int mid = (lo + hi + 1) >> 1;
                          if (sF[mid] > t) lo = mid; else hi = mid - 1; }
        unsigned prev = (lo == NBUCKC - 1) ? 0u : sF[lo + 1];
        unsigned j = t - prev;
        if (j < CAPC) {
            unsigned long long k =
                g_blist[((size_t)((n * 2 + 1) * NBUCKC + lo)) * CAPC + j];
            unsigned slot = atomicAdd(&scnt, 1u);
            if (slot < TOTAL_K) slist[slot] = (~(unsigned)k) | 0x80000000u;
        }
    }
    for (unsigned t = tid; t < totAB; t += 512) {
        int lo = 0, hi = NBUCKC - 1;
        while (lo < hi) { int mid = (lo + hi + 1) >> 1;
                          if (sB[mid] > t) lo = mid; else hi = mid - 1; }
        unsigned prev = (lo == NBUCKC - 1) ? 0u : sB[lo + 1];
        unsigned j = t - prev;
        if (j < CAPC) {
            unsigned long long k =
                g_blist[((size_t)((n * 2 + 0) * NBUCKC + lo)) * CAPC + j];
            unsigned slot = atomicAdd(&scnt, 1u);
            if (slot < TOTAL_K) slist[slot] = (~(unsigned)k);
        }
    }
    // boundary-bucket survivors (exactly sneed per class)
    for (unsigned i = tid; i < LF; i += 512) {
        if (kF[i] >= cutF) {
            unsigned slot = atomicAdd(&scnt, 1u);
            if (slot < TOTAL_K) slist[slot] = (~(unsigned)kF[i]) | 0x80000000u;
        }
    }
    for (unsigned i = tid; i < LB; i += 512) {
        if (kB[i] >= cutB) {
            unsigned slot = atomicAdd(&scnt, 1u);
            if (slot < TOTAL_K) slist[slot] = (~(unsigned)kB[i]);
        }
    }
    __syncthreads();
    unsigned cnt = scnt < TOTAL_K ? scnt : TOTAL_K;

    // pad-tail fg flag for anchor 0 (rare path: bg pool smaller than quota)
    if (tid == 0 && cnt < TOTAL_K) {
        float amax0 = g_amax[(size_t)n * AN + 0];    // a'=0 <-> a=0
        int lab0 = (amax0 >= POS_T) ? 1 : -1;
        if (lab0 != 1 && amax0 >= 0.0f) {
            float4 A4 = ((const float4*)anchors)[0];
            float4 d  = ((const float4*)(deltas + (size_t)n * AN * 4))[0];
            float b[4], areaA; bool valid;
            predbox(A4, d, b, &areaA, &valid);
            for (int m = 0; m < MG; m++) {
                float pm = spgm[m];
                if (pm <= amax0) {
                    float4 g = sg[m];
                    float ag = __fmul_rn(__fadd_rn(__fsub_rn(g.z, g.x), 1.0f),
                                         __fadd_rn(__fsub_rn(g.w, g.y), 1.0f));
                    float iw = __fadd_rn(__fsub_rn(fminf(b[2], g.z), fmaxf(b[0], g.x)), 1.0f);
                    float ih = __fadd_rn(__fsub_rn(fminf(b[3], g.w), fmaxf(b[1], g.y)), 1.0f);
                    if (iw > 0.0f && ih > 0.0f) {
                        float inter = __fmul_rn(iw, ih);
                        if (iou_div(inter, areaA, ag) == pm) lab0 = 1;
                    } else if (pm == 0.0f) lab0 = 1;
                }
            }
        }
        if (lab0 == 1 && keyf(rs[(size_t)n * AN + 0], 0) >= cutF) sfg0 = 1;
    }
    __syncthreads();

    // rank-sort by anchor index ascending, then write
    if (tid < (int)cnt) {
        unsigned e = slist[tid];
        unsigned ai = e & 0x7FFFFFFFu;
        unsigned rank = 0;
        for (unsigned j = 0; j < cnt; j++)
            rank += ((slist[j] & 0x7FFFFFFFu) < ai);
        write_out(out, n, rank, (int)ai, (e & 0x80000000u) != 0, sg,
                  anchors, deltas + (size_t)n * AN * 4);
    }
    if ((unsigned)tid >= cnt && tid < TOTAL_K) {
        write_out(out, n, (unsigned)tid, 0, sfg0 != 0, sg,
                  anchors, deltas + (size_t)n * AN * 4);
    }
}

// ----- launch ---------------------------------------------------------------
extern "C" void kernel_launch(void* const* d_in, const int* in_sizes, int n_in,
                              void* d_out, int out_size) {
    const float *anchors = nullptr, *gtb = nullptr, *deltas = nullptr, *rsc = nullptr;
    for (int i = 0; i < n_in; i++) {
        int s = in_sizes[i];
        if (s == AN * 4)           anchors = (const float*)d_in[i];
        else if (s == NI * MG * 4) gtb     = (const float*)d_in[i];
        else if (s == NI * AN * 4) deltas  = (const float*)d_in[i];
        else if (s == NI * AN)     rsc     = (const float*)d_in[i];
    }
    float* out = (float*)d_out;

    dim3 g1(NPOS / PCHUNK, NI, NTYPE);   // (16, 32, 9) = 4608 CTAs
    k_pass1<<<g1, PCHUNK>>>(anchors, gtb, deltas);
    k_pass2<<<g1, PCHUNK>>>(anchors, gtb, deltas, rsc);
    k_finish<<<NI, 512>>>(anchors, gtb, deltas, rsc, out);
}